// round 3
// baseline (speedup 1.0000x reference)
#include <cuda_runtime.h>

#define Hh 192
#define Wd 192
#define HW (Hh*Wd)
#define Nb 6
#define KG 20
#define KC 400
#define NA 403          // 400 ctrl + 3 affine
#define SA 408          // padded row stride (cols 403,404 = rhs, 405..407 zero pad)
#define NB 8            // LU panel width
#define NT 512          // threads in k_solve
#define LAMBDc 100.0f
#define BIGc 100000000.0f
#define EPSc 1e-9f
#define STEPc (2.0f/191.0f)

// round(linspace(0,191,20)) — data independent
__device__ __constant__ int c_ctrl[KG] =
    {0,10,20,30,40,50,60,70,80,90,101,111,121,131,141,151,161,171,181,191};

// ------- scratch (device globals, no allocs) -------
__device__ float g_cx[Nb*HW];
__device__ float g_cy[Nb*HW];
__device__ float g_dx[Nb*HW];
__device__ float g_dy[Nb*HW];
__device__ float g_m [Nb*HW];
__device__ __align__(16) float g_A[Nb][NA][SA];   // ~3.95 MB, L2 resident
__device__ __align__(16) float4 g_cw[Nb][KC];     // (sx, sy, w0, w1)
__device__ float g_aff[Nb][6];

// ============================================================
// Kernel 1: fused analytic-field backward warp
// ============================================================
__global__ void k_prepare(const float* __restrict__ duv,
                          const float* __restrict__ uv,
                          float* __restrict__ out_mask)
{
    int idx = blockIdx.x*blockDim.x + threadIdx.x;
    if (idx >= Nb*HW) return;

    float gx = uv[idx*2+0];
    float gy = uv[idx*2+1];
    float x = (gx + 1.0f)*0.5f*(Wd-1);
    float y = (gy + 1.0f)*0.5f*(Hh-1);
    float x0f = floorf(x), y0f = floorf(y);
    float wx = x - x0f,   wy = y - y0f;
    int x0 = (int)x0f, y0 = (int)y0f;

    float acx=0.f, acy=0.f, adx=0.f, ady=0.f, am=0.f;

    #pragma unroll
    for (int cyi = 0; cyi < 2; cyi++) {
        #pragma unroll
        for (int cxi = 0; cxi < 2; cxi++) {
            int xi = x0 + cxi, yi = y0 + cyi;
            float w = (cxi ? wx : 1.0f-wx) * (cyi ? wy : 1.0f-wy);
            if (xi >= 0 && xi < Wd && yi >= 0 && yi < Hh) {
                float du0 = duv[(yi*Wd+xi)*2+0];
                float du1 = duv[(yi*Wd+xi)*2+1];
                float vpix = (fabsf(du0) <= 1.0f && fabsf(du1) <= 1.0f) ? 1.0f : 0.0f;
                float bx = xi*STEPc - 1.0f;
                float by = yi*STEPc - 1.0f;
                acx += w*bx;
                acy += w*by;
                adx += w*(du0-bx)*vpix;
                ady += w*(du1-by)*vpix;
                am  += w*vpix;
            }
        }
    }
    float mth = (am > 0.5f) ? 1.0f : 0.0f;
    g_cx[idx]=acx; g_cy[idx]=acy; g_dx[idx]=adx; g_dy[idx]=ady; g_m[idx]=mth;
    out_mask[idx] = mth;
}

// ============================================================
// Kernel 2: build + blocked LU (deferred-swap partial pivoting)
//           + blocked back-sub. One 512-thread CTA per batch.
// ============================================================
__global__ void __launch_bounds__(NT, 1) k_solve()
{
    const int n   = blockIdx.x;
    const int tid = threadIdx.x;
    float* A = &g_A[n][0][0];

    __shared__ float2 sSrc[KC];
    __shared__ float  sM[KC];
    __shared__ __align__(16) float sP[NA][NB];   // panel (L multipliers + U11)
    __shared__ __align__(16) float sU[NB][SA];   // U strip
    __shared__ float sR[NA][2];                  // rhs / solution
    __shared__ float sD[NB][NB];                 // diag block for back-sub
    __shared__ int   sPivRow[NB];

    // ---- gather src / m at control pixels ----
    if (tid < KC) {
        int a = tid / KG, b = tid % KG;
        int pix = c_ctrl[a]*Wd + c_ctrl[b];
        sSrc[tid] = make_float2(g_cx[n*HW+pix], g_cy[n*HW+pix]);
        sM[tid]   = g_m[n*HW+pix];
    }
    __syncthreads();

    // ---- build augmented matrix ----
    for (int idx = tid; idx < NA*SA; idx += NT) {
        int i = idx / SA, j = idx - i*SA;
        float v = 0.0f;
        if (j < 405) {
            if (i < KC) {
                float2 si = sSrc[i];
                if (j < KC) {
                    float2 sj = sSrc[j];
                    float ddx = si.x - sj.x, ddy = si.y - sj.y;
                    float r2 = ddx*ddx + ddy*ddy;
                    v = 0.5f * r2 * __logf(r2 + EPSc);
                    if (i == j) v += LAMBDc + BIGc*(1.0f - sM[i]);
                } else if (j == 400) v = 1.0f;
                else if (j == 401) v = si.x;
                else if (j == 402) v = si.y;
                else if (j == 403) v = c_ctrl[i % KG]*STEPc - 1.0f;
                else               v = c_ctrl[i / KG]*STEPc - 1.0f;
            } else {
                int r = i - KC;
                if (j < KC) {
                    float2 sj = sSrc[j];
                    v = (r == 0) ? 1.0f : (r == 1 ? sj.x : sj.y);
                }
            }
        }
        A[idx] = v;
    }
    __syncthreads();

    // ---- blocked LU with partial pivoting (deferred trailing swaps) ----
    for (int kb = 0; kb < NA; kb += NB) {
        const int ke   = min(kb+NB, NA);
        const int bw   = ke - kb;
        const int nact = NA - kb;
        const int Lw   = 405 - ke;

        // load panel into SMEM (zero-fill cols >= bw)
        for (int idx = tid; idx < nact*NB; idx += NT) {
            int t = idx >> 3, s = idx & 7;
            sP[t][s] = (s < bw) ? A[(kb+t)*SA + kb + s] : 0.0f;
        }
        __syncthreads();

        // panel factorization: warp0 pivots+swaps, block eliminates
        for (int s = 0; s < bw; s++) {
            if (tid < 32) {
                float best = -1.0f; int bi = s;
                for (int t = s + tid; t < nact; t += 32) {
                    float v = fabsf(sP[t][s]);
                    if (v > best) { best = v; bi = t; }
                }
                #pragma unroll
                for (int off = 16; off; off >>= 1) {
                    float ov = __shfl_down_sync(0xffffffffu, best, off);
                    int   oi = __shfl_down_sync(0xffffffffu, bi,   off);
                    if (ov > best) { best = ov; bi = oi; }
                }
                int p = __shfl_sync(0xffffffffu, bi, 0);
                if (tid == 0) sPivRow[s] = p;
                if (p != s && tid < NB) {
                    float t0 = sP[s][tid]; sP[s][tid] = sP[p][tid]; sP[p][tid] = t0;
                }
            }
            __syncthreads();
            float inv = 1.0f / sP[s][s];
            int t = s + 1 + tid;
            if (t < nact) {
                float f = sP[t][s] * inv;
                sP[t][s] = f;
                #pragma unroll
                for (int j = 0; j < NB; j++)
                    if (j > s && j < bw) sP[t][j] -= f * sP[s][j];
            }
            __syncthreads();
        }

        // deferred row swaps on trailing columns [ke, 405)
        for (int j = tid; j < Lw; j += NT) {
            #pragma unroll
            for (int s = 0; s < NB; s++) {
                if (s < bw) {
                    int p = sPivRow[s];
                    if (p != s) {
                        float t1 = A[(kb+s)*SA + ke + j];
                        A[(kb+s)*SA + ke + j] = A[(kb+p)*SA + ke + j];
                        A[(kb+p)*SA + ke + j] = t1;
                    }
                }
            }
        }
        __syncthreads();

        // write back panel (L + U11)
        for (int idx = tid; idx < nact*bw; idx += NT) {
            int t = idx / bw, s = idx - t*bw;
            A[(kb+t)*SA + kb + s] = sP[t][s];
        }

        // load U strip (rows kb..ke-1, cols ke..ke+LpS)
        const int LpS = min(Lw + 3, 408 - ke);   // mult of 8 except last panel
        for (int idx = tid; idx < NB*LpS; idx += NT) {
            int r = idx / LpS, j = idx - r*LpS;
            sU[r][j] = (r < bw) ? A[(kb+r)*SA + ke + j] : 0.0f;
        }
        __syncthreads();

        // TRSM by unit-lower L11 (per-column, no sync inside)
        for (int j = tid; j < Lw; j += NT) {
            float col[NB];
            #pragma unroll
            for (int r = 0; r < NB; r++) col[r] = sU[r][j];
            #pragma unroll
            for (int r = 1; r < NB; r++) {
                if (r < bw) {
                    #pragma unroll
                    for (int s2 = 0; s2 < NB; s2++)
                        if (s2 < r) col[r] -= sP[r][s2]*col[s2];
                }
            }
            #pragma unroll
            for (int r = 0; r < NB; r++) if (r < bw) sU[r][j] = col[r];
        }
        __syncthreads();

        // write back U strip
        for (int idx = tid; idx < bw*Lw; idx += NT) {
            int r = idx / Lw, j = idx - r*Lw;
            A[(kb+r)*SA + ke + j] = sU[r][j];
        }

        // rank-8 trailing update, 8x8 register tiles
        const int nrows = NA - ke;
        if (nrows > 0) {
            const int nrt = (nrows + 7) >> 3;
            const int nct = (Lw + 3) >> 3;       // (Lw+3) is mult of 8 here
            const int ntile = nrt * nct;
            for (int tile = tid; tile < ntile; tile += NT) {
                int tr = tile / nct, tc = tile - tr*nct;
                int i0 = ke + (tr << 3);
                int j0 = tc << 3;
                int rmax = NA - i0;              // may exceed 8; guard below
                float4 acc[NB][2];
                #pragma unroll
                for (int r = 0; r < NB; r++) {
                    if (r < rmax) {
                        const float* ap = &A[(i0+r)*SA + ke + j0];
                        acc[r][0] = *(const float4*)(ap);
                        acc[r][1] = *(const float4*)(ap + 4);
                    }
                }
                #pragma unroll
                for (int s = 0; s < NB; s++) {
                    float4 u0 = *(const float4*)&sU[s][j0];
                    float4 u1 = *(const float4*)&sU[s][j0 + 4];
                    #pragma unroll
                    for (int r = 0; r < NB; r++) {
                        if (r < rmax) {
                            float f = sP[i0 - kb + r][s];
                            acc[r][0].x = fmaf(-f, u0.x, acc[r][0].x);
                            acc[r][0].y = fmaf(-f, u0.y, acc[r][0].y);
                            acc[r][0].z = fmaf(-f, u0.z, acc[r][0].z);
                            acc[r][0].w = fmaf(-f, u0.w, acc[r][0].w);
                            acc[r][1].x = fmaf(-f, u1.x, acc[r][1].x);
                            acc[r][1].y = fmaf(-f, u1.y, acc[r][1].y);
                            acc[r][1].z = fmaf(-f, u1.z, acc[r][1].z);
                            acc[r][1].w = fmaf(-f, u1.w, acc[r][1].w);
                        }
                    }
                }
                #pragma unroll
                for (int r = 0; r < NB; r++) {
                    if (r < rmax) {
                        float* ap = &A[(i0+r)*SA + ke + j0];
                        *(float4*)(ap)     = acc[r][0];
                        *(float4*)(ap + 4) = acc[r][1];
                    }
                }
            }
        }
        __syncthreads();
    }

    // ---- blocked back substitution (2 rhs) ----
    for (int i = tid; i < NA; i += NT) {
        sR[i][0] = A[i*SA + 403];
        sR[i][1] = A[i*SA + 404];
    }
    __syncthreads();

    for (int kb = 400; kb >= 0; kb -= NB) {
        int ke = min(kb+NB, NA);
        int bw = ke - kb;
        // preload diag block
        if (tid < 64) {
            int r = tid >> 3, c = tid & 7;
            if (r < bw && c < bw) sD[r][c] = A[(kb+r)*SA + kb + c];
        }
        __syncthreads();
        if (tid == 0) {
            for (int k = bw-1; k >= 0; k--) {
                float x0 = sR[kb+k][0], x1 = sR[kb+k][1];
                for (int j = k+1; j < bw; j++) {
                    float u = sD[k][j];
                    x0 -= u * sR[kb+j][0];
                    x1 -= u * sR[kb+j][1];
                }
                float inv = 1.0f / sD[k][k];
                sR[kb+k][0] = x0*inv;
                sR[kb+k][1] = x1*inv;
            }
        }
        __syncthreads();
        if (tid < kb) {
            float a0 = sR[tid][0], a1 = sR[tid][1];
            #pragma unroll
            for (int s = 0; s < NB; s++) {
                if (s < bw) {
                    float u = A[tid*SA + kb + s];
                    a0 -= u * sR[kb+s][0];
                    a1 -= u * sR[kb+s][1];
                }
            }
            sR[tid][0] = a0; sR[tid][1] = a1;
        }
        __syncthreads();
    }

    // ---- pack (src, wgt) + affine for eval ----
    if (tid < KC)
        g_cw[n][tid] = make_float4(sSrc[tid].x, sSrc[tid].y, sR[tid][0], sR[tid][1]);
    if (tid >= KC && tid < NA) {
        int r = tid - KC;
        g_aff[n][r*2+0] = sR[tid][0];
        g_aff[n][r*2+1] = sR[tid][1];
    }
}

// ============================================================
// Kernel 3: fused TPS eval (3 FD queries in one pass) + compose
// ============================================================
__global__ void __launch_bounds__(256) k_eval(float* __restrict__ out)
{
    __shared__ __align__(16) float4 scw[KC];
    __shared__ float saff[6];

    const int bpn = HW/256;
    int n  = blockIdx.x / bpn;
    int p  = (blockIdx.x - n*bpn)*256 + threadIdx.x;

    for (int i = threadIdx.x; i < KC; i += 256) scw[i] = g_cw[n][i];
    if (threadIdx.x < 6) saff[threadIdx.x] = g_aff[n][threadIdx.x];
    __syncthreads();

    int gi = n*HW + p;
    float qx = g_cx[gi], qy = g_cy[gi];
    float m  = g_m[gi];

    const float DX  = STEPc;
    const float DX2 = DX*DX;
    const float TDX = 2.0f*DX;

    float a00=0.f, a01=0.f, ax0=0.f, ax1=0.f, ay0=0.f, ay1=0.f;

    #pragma unroll 4
    for (int c = 0; c < KC; c++) {
        float4 cw = scw[c];
        float ddx = qx - cw.x;
        float ddy = qy - cw.y;
        float r2  = fmaf(ddx, ddx, ddy*ddy);
        float r2x = r2 + fmaf(TDX, ddx, DX2);
        float r2y = r2 + fmaf(TDX, ddy, DX2);
        float u0 = 0.5f*r2 *__logf(r2  + EPSc);
        float ux = 0.5f*r2x*__logf(r2x + EPSc);
        float uy = 0.5f*r2y*__logf(r2y + EPSc);
        a00 = fmaf(u0, cw.z, a00);  a01 = fmaf(u0, cw.w, a01);
        ax0 = fmaf(ux, cw.z, ax0);  ax1 = fmaf(ux, cw.w, ax1);
        ay0 = fmaf(uy, cw.z, ay0);  ay1 = fmaf(uy, cw.w, ay1);
    }

    float qxx = qx + DX, qyy = qy + DX;
    float c00 = a00 + saff[0] + qx *saff[2] + qy *saff[4];
    float c01 = a01 + saff[1] + qx *saff[3] + qy *saff[5];
    float cx0 = ax0 + saff[0] + qxx*saff[2] + qy *saff[4];
    float cx1 = ax1 + saff[1] + qxx*saff[3] + qy *saff[5];
    float cy0 = ay0 + saff[0] + qx *saff[2] + qyy*saff[4];
    float cy1 = ay1 + saff[1] + qx *saff[3] + qyy*saff[5];

    const float invDX = 1.0f/STEPc;
    float av = (cx0 - c00)*invDX;
    float bv = (cx1 - c01)*invDX;
    float cv = (cy0 - c00)*invDX;
    float dv = (cy1 - c01)*invDX;

    float d0 = g_dx[gi], d1 = g_dy[gi];
    float dn0 = av*d0 + cv*d1;
    float dn1 = bv*d0 + dv*d1;

    int w = p % Wd, h = p / Wd;
    float bx = w*STEPc - 1.0f;
    float by = h*STEPc - 1.0f;
    float o0 = (bx + dn0)*m - 2.0f*(1.0f - m);
    float o1 = (by + dn1)*m - 2.0f*(1.0f - m);
    out[gi*2+0] = o0;
    out[gi*2+1] = o1;
}

// ============================================================
extern "C" void kernel_launch(void* const* d_in, const int* in_sizes, int n_in,
                              void* d_out, int out_size)
{
    const float* in0 = (const float*)d_in[0];
    const float* in1 = (const float*)d_in[1];
    const float* duv;
    const float* uv;
    if (in_sizes[0] == 2*HW) { duv = in0; uv = in1; }
    else                     { duv = in1; uv = in0; }

    float* out = (float*)d_out;
    float* out_mask = out + (size_t)Nb*HW*2;

    k_prepare<<<(Nb*HW + 255)/256, 256>>>(duv, uv, out_mask);
    k_solve<<<Nb, NT>>>();
    k_eval<<<Nb*(HW/256), 256>>>(out);
}

// round 4
// speedup vs baseline: 1.7304x; 1.7304x over previous
#include <cuda_runtime.h>

#define Hh 192
#define Wd 192
#define HW (Hh*Wd)
#define Nb 6
#define KG 20
#define KC 400
#define NA 403          // 400 ctrl + 3 affine
#define SA 408          // padded row stride (403,404 = rhs, 405..407 zero pad)
#define PBW 32          // LU panel width
#define NPAN 13
#define PROWS 404       // panel SMEM row stride
#define LAMBDc 100.0f
#define BIGc 100000000.0f
#define EPSc 1e-9f
#define STEPc (2.0f/191.0f)

__device__ __constant__ int c_ctrl[KG] =
    {0,10,20,30,40,50,60,70,80,90,101,111,121,131,141,151,161,171,181,191};

// ------- scratch (device globals, no allocs) -------
__device__ float g_cx[Nb*HW];
__device__ float g_cy[Nb*HW];
__device__ float g_dx[Nb*HW];
__device__ float g_dy[Nb*HW];
__device__ float g_m [Nb*HW];
__device__ __align__(16) float g_A[Nb][NA][SA];   // ~3.95 MB, L2 resident
__device__ int g_piv[Nb][NPAN][PBW];
__device__ __align__(16) float4 g_cw[Nb][KC];
__device__ float g_aff[Nb][6];

// ============================================================
// Kernel 1: fused analytic-field backward warp
// ============================================================
__global__ void k_prepare(const float* __restrict__ duv,
                          const float* __restrict__ uv,
                          float* __restrict__ out_mask)
{
    int idx = blockIdx.x*blockDim.x + threadIdx.x;
    if (idx >= Nb*HW) return;

    float gx = uv[idx*2+0];
    float gy = uv[idx*2+1];
    float x = (gx + 1.0f)*0.5f*(Wd-1);
    float y = (gy + 1.0f)*0.5f*(Hh-1);
    float x0f = floorf(x), y0f = floorf(y);
    float wx = x - x0f,   wy = y - y0f;
    int x0 = (int)x0f, y0 = (int)y0f;

    float acx=0.f, acy=0.f, adx=0.f, ady=0.f, am=0.f;

    #pragma unroll
    for (int cyi = 0; cyi < 2; cyi++) {
        #pragma unroll
        for (int cxi = 0; cxi < 2; cxi++) {
            int xi = x0 + cxi, yi = y0 + cyi;
            float w = (cxi ? wx : 1.0f-wx) * (cyi ? wy : 1.0f-wy);
            if (xi >= 0 && xi < Wd && yi >= 0 && yi < Hh) {
                float du0 = duv[(yi*Wd+xi)*2+0];
                float du1 = duv[(yi*Wd+xi)*2+1];
                float vpix = (fabsf(du0) <= 1.0f && fabsf(du1) <= 1.0f) ? 1.0f : 0.0f;
                float bx = xi*STEPc - 1.0f;
                float by = yi*STEPc - 1.0f;
                acx += w*bx;
                acy += w*by;
                adx += w*(du0-bx)*vpix;
                ady += w*(du1-by)*vpix;
                am  += w*vpix;
            }
        }
    }
    float mth = (am > 0.5f) ? 1.0f : 0.0f;
    g_cx[idx]=acx; g_cy[idx]=acy; g_dx[idx]=adx; g_dy[idx]=ady; g_m[idx]=mth;
    out_mask[idx] = mth;
}

// ============================================================
// Kernel 2: build augmented matrix (chip-wide, coalesced writes)
// ============================================================
__global__ void k_build()
{
    int idx = blockIdx.x*blockDim.x + threadIdx.x;
    if (idx >= Nb*NA*SA) return;
    int n = idx / (NA*SA);
    int rem = idx - n*NA*SA;
    int i = rem / SA, j = rem - i*SA;
    float v = 0.0f;
    if (j < 405) {
        if (i < KC) {
            int pa = c_ctrl[i/KG]*Wd + c_ctrl[i%KG];
            float six = g_cx[n*HW+pa], siy = g_cy[n*HW+pa];
            if (j < KC) {
                int pb = c_ctrl[j/KG]*Wd + c_ctrl[j%KG];
                float sjx = g_cx[n*HW+pb], sjy = g_cy[n*HW+pb];
                float ddx = six-sjx, ddy = siy-sjy;
                float r2 = ddx*ddx + ddy*ddy;
                v = 0.5f*r2*__logf(r2+EPSc);
                if (i == j) v += LAMBDc + BIGc*(1.0f - g_m[n*HW+pa]);
            } else if (j == 400) v = 1.0f;
            else if (j == 401) v = six;
            else if (j == 402) v = siy;
            else if (j == 403) v = c_ctrl[i%KG]*STEPc - 1.0f;
            else               v = c_ctrl[i/KG]*STEPc - 1.0f;
        } else {
            int r = i - KC;
            if (j < KC) {
                int pb = c_ctrl[j/KG]*Wd + c_ctrl[j%KG];
                v = (r==0) ? 1.0f : ((r==1) ? g_cx[n*HW+pb] : g_cy[n*HW+pb]);
            }
        }
    }
    g_A[n][i][j] = v;
}

// ============================================================
// Kernel 3: panel factorization (rows kb..NA, cols kb..kb+bw) in SMEM
// ============================================================
__global__ void __launch_bounds__(512, 1) k_panel(int kb, int bw)
{
    extern __shared__ float sPan[];          // [bw][PROWS] column-major
    __shared__ unsigned sWkey[16];
    __shared__ int      sWrow[16];
    __shared__ int      sPivA[PBW];
    __shared__ float    sInv;

    const int n = blockIdx.x;
    const int tid = threadIdx.x;
    const int nact = NA - kb;
    float* A = &g_A[n][0][0];

    // load panel (coalesced over j)
    for (int idx = tid; idx < nact*bw; idx += 512) {
        int t = idx / bw, j = idx - t*bw;
        sPan[j*PROWS + t] = A[(kb+t)*SA + kb + j];
    }
    __syncthreads();

    for (int s = 0; s < bw; s++) {
        // block argmax over column s, rows [s, nact)
        float v = 0.0f;
        int t = tid;
        if (t >= s && t < nact) v = fabsf(sPan[s*PROWS + t]);
        unsigned bits = __float_as_uint(v);
        unsigned wmax = __reduce_max_sync(0xffffffffu, bits);
        unsigned ball = __ballot_sync(0xffffffffu, bits == wmax);
        if ((tid & 31) == (__ffs(ball) - 1)) {
            sWkey[tid>>5] = (wmax & 0xFFFFFFF0u) | (unsigned)(tid>>5);
            sWrow[tid>>5] = t;
        }
        __syncthreads();
        if (tid < 32) {
            unsigned key = (tid < 16) ? sWkey[tid] : 0u;
            unsigned m2 = __reduce_max_sync(0xffffffffu, key);
            int p = sWrow[m2 & 15u];
            if (tid == 0) sPivA[s] = p;
            if (p != s && tid < bw) {
                float a = sPan[tid*PROWS + s], b = sPan[tid*PROWS + p];
                sPan[tid*PROWS + s] = b;
                sPan[tid*PROWS + p] = a;
            }
            __syncwarp();
            if (tid == 0) sInv = 1.0f / sPan[s*PROWS + s];
        }
        __syncthreads();
        float inv = sInv;
        if (t > s && t < nact) {
            float f = sPan[s*PROWS + t] * inv;
            sPan[s*PROWS + t] = f;
            for (int j = s+1; j < bw; j++)
                sPan[j*PROWS + t] -= f * sPan[j*PROWS + s];
        }
        __syncthreads();
    }

    // writeback (L + U11) and pivots
    for (int idx = tid; idx < nact*bw; idx += 512) {
        int t = idx / bw, j = idx - t*bw;
        A[(kb+t)*SA + kb + j] = sPan[j*PROWS + t];
    }
    if (tid < bw) g_piv[n][kb/PBW][tid] = sPivA[tid];
}

// ============================================================
// Kernel 4: per column-slice: row swaps + TRSM + rank-bw GEMM update
// grid (ncs, Nb), 256 threads
// ============================================================
__global__ void __launch_bounds__(256, 2) k_update(int kb, int bw)
{
    const int cs = blockIdx.x, n = blockIdx.y, tid = threadIdx.x;
    const int ke = kb + bw;
    const int c0 = ke + cs*32;
    const int cw = min(32, 405 - c0);
    const int nact = NA - kb;
    float* A = &g_A[n][0][0];

    __shared__ int   sPerm[NA];
    __shared__ int   sMoved[2*PBW];
    __shared__ int   sNmov;
    __shared__ float sBuf[2*PBW][32];
    __shared__ float sL[PBW][PBW+1];
    __shared__ float sB[PBW][33];
    __shared__ float sL2[128][PBW+1];

    // ---- build final row permutation for this panel ----
    for (int i = tid; i < nact; i += 256) sPerm[i] = i;
    if (tid == 0) sNmov = 0;
    __syncthreads();
    if (tid == 0) {
        const int* piv = g_piv[n][kb/PBW];
        for (int s = 0; s < bw; s++) {
            int p = piv[s];
            if (p != s) { int t0 = sPerm[s]; sPerm[s] = sPerm[p]; sPerm[p] = t0; }
        }
    }
    __syncthreads();
    for (int i = tid; i < nact; i += 256)
        if (sPerm[i] != i) { int sl = atomicAdd(&sNmov, 1); sMoved[sl] = i; }
    __syncthreads();
    int nmov = sNmov;
    // gather then scatter (moved set <= 2*bw)
    for (int idx = tid; idx < nmov*cw; idx += 256) {
        int mi = idx / cw, j = idx - mi*cw;
        sBuf[mi][j] = A[(kb + sPerm[sMoved[mi]])*SA + c0 + j];
    }
    __syncthreads();
    for (int idx = tid; idx < nmov*cw; idx += 256) {
        int mi = idx / cw, j = idx - mi*cw;
        A[(kb + sMoved[mi])*SA + c0 + j] = sBuf[mi][j];
    }
    // ---- load L11 ----
    for (int idx = tid; idx < bw*bw; idx += 256) {
        int r = idx / bw, s2 = idx - r*bw;
        sL[r][s2] = A[(kb+r)*SA + kb + s2];
    }
    __syncthreads();

    // ---- TRSM: unit-lower L11 solve, one thread per column ----
    if (tid < cw) {
        int j = tid;
        float c[PBW];
        #pragma unroll
        for (int r = 0; r < PBW; r++) c[r] = (r < bw) ? A[(kb+r)*SA + c0 + j] : 0.0f;
        #pragma unroll
        for (int r = 1; r < PBW; r++) {
            if (r < bw) {
                #pragma unroll
                for (int s2 = 0; s2 < PBW; s2++)
                    if (s2 < r) c[r] -= sL[r][s2]*c[s2];
            }
        }
        #pragma unroll
        for (int r = 0; r < PBW; r++) {
            if (r < bw) { sB[r][j] = c[r]; A[(kb+r)*SA + c0 + j] = c[r]; }
        }
    }
    __syncthreads();

    // ---- rank-bw trailing update, 128-row chunks, 4x4 reg tiles ----
    const int tr = tid >> 3;      // 0..31
    const int tc = tid & 7;       // 0..7
    for (int i0 = ke; i0 < NA; i0 += 128) {
        int chunk = min(128, NA - i0);
        for (int idx = tid; idx < 128*32; idx += 256) {
            int r = idx >> 5, s2 = idx & 31;
            sL2[r][s2] = (s2 < bw && r < chunk) ? A[(i0+r)*SA + kb + s2] : 0.0f;
        }
        __syncthreads();
        float acc[4][4];
        #pragma unroll
        for (int a = 0; a < 4; a++) {
            int row = tr + 32*a;
            #pragma unroll
            for (int b = 0; b < 4; b++) {
                int col = tc + 8*b;
                acc[a][b] = (row < chunk && col < cw) ? A[(i0+row)*SA + c0 + col] : 0.0f;
            }
        }
        #pragma unroll
        for (int s2 = 0; s2 < PBW; s2++) {
            float l0 = sL2[tr][s2], l1 = sL2[tr+32][s2];
            float l2 = sL2[tr+64][s2], l3 = sL2[tr+96][s2];
            float u0 = sB[s2][tc],    u1 = sB[s2][tc+8];
            float u2 = sB[s2][tc+16], u3 = sB[s2][tc+24];
            acc[0][0] -= l0*u0; acc[0][1] -= l0*u1; acc[0][2] -= l0*u2; acc[0][3] -= l0*u3;
            acc[1][0] -= l1*u0; acc[1][1] -= l1*u1; acc[1][2] -= l1*u2; acc[1][3] -= l1*u3;
            acc[2][0] -= l2*u0; acc[2][1] -= l2*u1; acc[2][2] -= l2*u2; acc[2][3] -= l2*u3;
            acc[3][0] -= l3*u0; acc[3][1] -= l3*u1; acc[3][2] -= l3*u2; acc[3][3] -= l3*u3;
        }
        #pragma unroll
        for (int a = 0; a < 4; a++) {
            int row = tr + 32*a;
            #pragma unroll
            for (int b = 0; b < 4; b++) {
                int col = tc + 8*b;
                if (row < chunk && col < cw) A[(i0+row)*SA + c0 + col] = acc[a][b];
            }
        }
        __syncthreads();
    }
}

// ============================================================
// Kernel 5: blocked back substitution (warp-systolic diag solves)
// ============================================================
__global__ void __launch_bounds__(512, 1) k_backsub()
{
    const int n = blockIdx.x, tid = threadIdx.x;
    float* A = &g_A[n][0][0];
    __shared__ float sR[NA][2];

    for (int i = tid; i < NA; i += 512) {
        sR[i][0] = A[i*SA + 403];
        sR[i][1] = A[i*SA + 404];
    }
    __syncthreads();

    for (int kb = 400; kb >= 0; kb -= 8) {
        int bw = min(8, NA - kb);
        if (tid < 32) {
            int r = tid;
            float d[8] = {0,0,0,0,0,0,0,0};
            float x0 = 0.f, x1 = 0.f;
            if (r < bw) {
                float4 q0 = *(const float4*)&A[(kb+r)*SA + kb];
                float4 q1 = *(const float4*)&A[(kb+r)*SA + kb + 4];
                d[0]=q0.x; d[1]=q0.y; d[2]=q0.z; d[3]=q0.w;
                d[4]=q1.x; d[5]=q1.y; d[6]=q1.z; d[7]=q1.w;
                x0 = sR[kb+r][0]; x1 = sR[kb+r][1];
            }
            #pragma unroll
            for (int k = 7; k >= 0; k--) {
                if (k < bw) {
                    float xk0 = 0.f, xk1 = 0.f;
                    if (r == k) { float iv = 1.0f/d[k]; xk0 = x0*iv; xk1 = x1*iv; }
                    xk0 = __shfl_sync(0xffffffffu, xk0, k);
                    xk1 = __shfl_sync(0xffffffffu, xk1, k);
                    if (r < k)  { x0 -= d[k]*xk0; x1 -= d[k]*xk1; }
                    if (r == k) { x0 = xk0; x1 = xk1; }
                }
            }
            if (r < bw) { sR[kb+r][0] = x0; sR[kb+r][1] = x1; }
        }
        __syncthreads();
        if (tid < kb) {
            float4 q0 = *(const float4*)&A[tid*SA + kb];
            float4 q1 = *(const float4*)&A[tid*SA + kb + 4];
            float u[8] = {q0.x,q0.y,q0.z,q0.w,q1.x,q1.y,q1.z,q1.w};
            float a0 = sR[tid][0], a1 = sR[tid][1];
            #pragma unroll
            for (int s = 0; s < 8; s++) {
                if (s < bw) { a0 -= u[s]*sR[kb+s][0]; a1 -= u[s]*sR[kb+s][1]; }
            }
            sR[tid][0] = a0; sR[tid][1] = a1;
        }
        __syncthreads();
    }

    if (tid < KC) {
        int a = tid / KG, b = tid % KG;
        int pix = c_ctrl[a]*Wd + c_ctrl[b];
        g_cw[n][tid] = make_float4(g_cx[n*HW+pix], g_cy[n*HW+pix], sR[tid][0], sR[tid][1]);
    }
    if (tid >= KC && tid < NA) {
        int r = tid - KC;
        g_aff[n][r*2+0] = sR[tid][0];
        g_aff[n][r*2+1] = sR[tid][1];
    }
}

// ============================================================
// Kernel 6: fused TPS eval (3 FD queries in one pass) + compose
// ============================================================
__global__ void __launch_bounds__(256) k_eval(float* __restrict__ out)
{
    __shared__ __align__(16) float4 scw[KC];
    __shared__ float saff[6];

    const int bpn = HW/256;
    int n  = blockIdx.x / bpn;
    int p  = (blockIdx.x - n*bpn)*256 + threadIdx.x;

    for (int i = threadIdx.x; i < KC; i += 256) scw[i] = g_cw[n][i];
    if (threadIdx.x < 6) saff[threadIdx.x] = g_aff[n][threadIdx.x];
    __syncthreads();

    int gi = n*HW + p;
    float qx = g_cx[gi], qy = g_cy[gi];
    float m  = g_m[gi];

    const float DX  = STEPc;
    const float DX2 = DX*DX;
    const float TDX = 2.0f*DX;

    float a00=0.f, a01=0.f, ax0=0.f, ax1=0.f, ay0=0.f, ay1=0.f;

    #pragma unroll 4
    for (int c = 0; c < KC; c++) {
        float4 cw = scw[c];
        float ddx = qx - cw.x;
        float ddy = qy - cw.y;
        float r2  = fmaf(ddx, ddx, ddy*ddy);
        float r2x = r2 + fmaf(TDX, ddx, DX2);
        float r2y = r2 + fmaf(TDX, ddy, DX2);
        float u0 = 0.5f*r2 *__logf(r2  + EPSc);
        float ux = 0.5f*r2x*__logf(r2x + EPSc);
        float uy = 0.5f*r2y*__logf(r2y + EPSc);
        a00 = fmaf(u0, cw.z, a00);  a01 = fmaf(u0, cw.w, a01);
        ax0 = fmaf(ux, cw.z, ax0);  ax1 = fmaf(ux, cw.w, ax1);
        ay0 = fmaf(uy, cw.z, ay0);  ay1 = fmaf(uy, cw.w, ay1);
    }

    float qxx = qx + DX, qyy = qy + DX;
    float c00 = a00 + saff[0] + qx *saff[2] + qy *saff[4];
    float c01 = a01 + saff[1] + qx *saff[3] + qy *saff[5];
    float cx0 = ax0 + saff[0] + qxx*saff[2] + qy *saff[4];
    float cx1 = ax1 + saff[1] + qxx*saff[3] + qy *saff[5];
    float cy0 = ay0 + saff[0] + qx *saff[2] + qyy*saff[4];
    float cy1 = ay1 + saff[1] + qx *saff[3] + qyy*saff[5];

    const float invDX = 1.0f/STEPc;
    float av = (cx0 - c00)*invDX;
    float bv = (cx1 - c01)*invDX;
    float cv = (cy0 - c00)*invDX;
    float dv = (cy1 - c01)*invDX;

    float d0 = g_dx[gi], d1 = g_dy[gi];
    float dn0 = av*d0 + cv*d1;
    float dn1 = bv*d0 + dv*d1;

    int w = p % Wd, h = p / Wd;
    float bx = w*STEPc - 1.0f;
    float by = h*STEPc - 1.0f;
    float o0 = (bx + dn0)*m - 2.0f*(1.0f - m);
    float o1 = (by + dn1)*m - 2.0f*(1.0f - m);
    out[gi*2+0] = o0;
    out[gi*2+1] = o1;
}

// ============================================================
extern "C" void kernel_launch(void* const* d_in, const int* in_sizes, int n_in,
                              void* d_out, int out_size)
{
    const float* in0 = (const float*)d_in[0];
    const float* in1 = (const float*)d_in[1];
    const float* duv;
    const float* uv;
    if (in_sizes[0] == 2*HW) { duv = in0; uv = in1; }
    else                     { duv = in1; uv = in0; }

    float* out = (float*)d_out;
    float* out_mask = out + (size_t)Nb*HW*2;

    const int panelSmem = PBW*PROWS*4;   // 51712 B
    cudaFuncSetAttribute(k_panel, cudaFuncAttributeMaxDynamicSharedMemorySize, panelSmem);

    k_prepare<<<(Nb*HW + 255)/256, 256>>>(duv, uv, out_mask);
    k_build<<<(Nb*NA*SA + 255)/256, 256>>>();

    for (int pan = 0; pan < NPAN; pan++) {
        int kb = pan*PBW;
        int bw = (NA - kb < PBW) ? (NA - kb) : PBW;
        k_panel<<<Nb, 512, panelSmem>>>(kb, bw);
        int ke = kb + bw;
        int Lw = 405 - ke;
        if (Lw > 0) {
            int ncs = (Lw + 31)/32;
            k_update<<<dim3(ncs, Nb), 256>>>(kb, bw);
        }
    }

    k_backsub<<<Nb, 512>>>();
    k_eval<<<Nb*(HW/256), 256>>>(out);
}

// round 9
// speedup vs baseline: 2.2704x; 1.3120x over previous
#include <cuda_runtime.h>

#define Hh 192
#define Wd 192
#define HW (Hh*Wd)
#define Nb 6
#define KG 20
#define KC 400
#define NA 403          // 400 ctrl + 3 affine
#define SA 408          // padded row stride (403,404 = rhs, 405..407 pad)
#define PBW 32          // panel/block width
#define NPAN 13
#define LWpad 376
#define LAMBDc 100.0f
#define BIGc 100000000.0f
#define EPSc 1e-9f
#define STEPc (2.0f/191.0f)

__device__ __constant__ int c_ctrl[KG] =
    {0,10,20,30,40,50,60,70,80,90,101,111,121,131,141,151,161,171,181,191};

// ------- scratch (device globals, no allocs) -------
__device__ float g_cx[Nb*HW];
__device__ float g_cy[Nb*HW];
__device__ float g_dx[Nb*HW];
__device__ float g_dy[Nb*HW];
__device__ float g_m [Nb*HW];
__device__ __align__(16) float g_A[Nb][NA][SA];   // ~3.95 MB, L2 resident
__device__ __align__(16) float4 g_cw[Nb][KC];     // (sx, sy, w0*, w1*) pre-scaled
__device__ float g_aff[Nb][6];

// ============================================================
// Kernel 1: fused analytic-field backward warp
// ============================================================
__global__ void k_prepare(const float* __restrict__ duv,
                          const float* __restrict__ uv,
                          float* __restrict__ out_mask)
{
    int idx = blockIdx.x*blockDim.x + threadIdx.x;
    if (idx >= Nb*HW) return;

    float gx = uv[idx*2+0];
    float gy = uv[idx*2+1];
    float x = (gx + 1.0f)*0.5f*(Wd-1);
    float y = (gy + 1.0f)*0.5f*(Hh-1);
    float x0f = floorf(x), y0f = floorf(y);
    float wx = x - x0f,   wy = y - y0f;
    int x0 = (int)x0f, y0 = (int)y0f;

    float acx=0.f, acy=0.f, adx=0.f, ady=0.f, am=0.f;

    #pragma unroll
    for (int cyi = 0; cyi < 2; cyi++) {
        #pragma unroll
        for (int cxi = 0; cxi < 2; cxi++) {
            int xi = x0 + cxi, yi = y0 + cyi;
            float w = (cxi ? wx : 1.0f-wx) * (cyi ? wy : 1.0f-wy);
            if (xi >= 0 && xi < Wd && yi >= 0 && yi < Hh) {
                float du0 = duv[(yi*Wd+xi)*2+0];
                float du1 = duv[(yi*Wd+xi)*2+1];
                float vpix = (fabsf(du0) <= 1.0f && fabsf(du1) <= 1.0f) ? 1.0f : 0.0f;
                float bx = xi*STEPc - 1.0f;
                float by = yi*STEPc - 1.0f;
                acx += w*bx;
                acy += w*by;
                adx += w*(du0-bx)*vpix;
                ady += w*(du1-by)*vpix;
                am  += w*vpix;
            }
        }
    }
    float mth = (am > 0.5f) ? 1.0f : 0.0f;
    g_cx[idx]=acx; g_cy[idx]=acy; g_dx[idx]=adx; g_dy[idx]=ady; g_m[idx]=mth;
    out_mask[idx] = mth;
}

// ============================================================
// Kernel 2: build augmented matrix (chip-wide, coalesced)
// ============================================================
__global__ void k_build()
{
    int idx = blockIdx.x*blockDim.x + threadIdx.x;
    if (idx >= Nb*NA*SA) return;
    int n = idx / (NA*SA);
    int rem = idx - n*NA*SA;
    int i = rem / SA, j = rem - i*SA;
    float v = 0.0f;
    if (j < 405) {
        if (i < KC) {
            int pa = c_ctrl[i/KG]*Wd + c_ctrl[i%KG];
            float six = g_cx[n*HW+pa], siy = g_cy[n*HW+pa];
            if (j < KC) {
                int pb = c_ctrl[j/KG]*Wd + c_ctrl[j%KG];
                float sjx = g_cx[n*HW+pb], sjy = g_cy[n*HW+pb];
                float ddx = six-sjx, ddy = siy-sjy;
                float r2 = ddx*ddx + ddy*ddy;
                v = 0.5f*r2*__logf(r2+EPSc);
                if (i == j) v += LAMBDc + BIGc*(1.0f - g_m[n*HW+pa]);
            } else if (j == 400) v = 1.0f;
            else if (j == 401) v = six;
            else if (j == 402) v = siy;
            else if (j == 403) v = c_ctrl[i%KG]*STEPc - 1.0f;
            else               v = c_ctrl[i/KG]*STEPc - 1.0f;
        } else {
            int r = i - KC;
            if (j < KC) {
                int pb = c_ctrl[j/KG]*Wd + c_ctrl[j%KG];
                v = (r==0) ? 1.0f : ((r==1) ? g_cx[n*HW+pb] : g_cy[n*HW+pb]);
            }
        }
    }
    g_A[n][i][j] = v;
}

// ============================================================
// Kernel 3: panel factorization — block LU (warp0, in-block pivoting,
//   register-resident) + both TRSMs. One CTA per batch.
// ============================================================
__global__ void __launch_bounds__(512, 1) k_factor(int kb, int bw)
{
    const int n = blockIdx.x, tid = threadIdx.x;
    const int lane = tid & 31, wid = tid >> 5;
    const int ke = kb + bw;
    const int M  = NA - ke;          // trailing rows
    const int Lw = 405 - ke;         // trailing cols incl rhs
    float* A = &g_A[n][0][0];

    __shared__ float sBlk[PBW][PBW+1];   // logical-order block (L\U)
    __shared__ float sInvD[PBW];
    __shared__ int   sPerm[PBW];
    extern __shared__ float sDyn[];
    float* sStrip = sDyn;                // [PBW][LWpad]
    float* sA21   = sDyn + PBW*LWpad;    // [<=371][PBW+1]

    if (wid > 0) {
        // warps 1..15: stage A21 while warp 0 factorizes the block
        for (int idx = tid - 32; idx < M*PBW; idx += 480) {
            int r = idx >> 5, j = idx & 31;
            sA21[r*(PBW+1) + j] = (j < bw) ? A[(ke+r)*SA + kb + j] : 0.0f;
        }
    } else {
        // ---- warp 0: 32x32 register LU, in-block partial pivoting ----
        float a[PBW];
        #pragma unroll
        for (int j = 0; j < PBW; j++)
            a[j] = (lane < bw && j < bw) ? A[(kb+lane)*SA + kb + j] : 0.0f;
        bool mydone = (lane >= bw);
        int myslot = -1;
        #pragma unroll
        for (int s = 0; s < PBW; s++) {
            if (s < bw) {
                float v = mydone ? 0.0f : fabsf(a[s]);
                unsigned key = mydone ? 0u
                    : ((__float_as_uint(v) & 0xFFFFFFE0u) | (unsigned)lane);
                unsigned kmax = __reduce_max_sync(0xffffffffu, key);
                int p = (int)(kmax & 31u);
                float piv = __shfl_sync(0xffffffffu, a[s], p);
                float inv = 1.0f / piv;
                if (lane == p) { mydone = true; myslot = s; sPerm[s] = lane; sInvD[s] = inv; }
                float f = mydone ? 0.0f : a[s]*inv;
                if (!mydone) a[s] = f;
                #pragma unroll
                for (int j = 0; j < PBW; j++) {
                    if (j > s) {
                        float u = __shfl_sync(0xffffffffu, a[j], p);
                        if (!mydone) a[j] = fmaf(-f, u, a[j]);
                    }
                }
            }
        }
        if (myslot >= 0) {
            #pragma unroll
            for (int j = 0; j < PBW; j++) sBlk[myslot][j] = a[j];
        }
    }
    __syncthreads();

    // gather permuted strip rows (coalesced)
    for (int idx = tid; idx < bw*Lw; idx += 512) {
        int r = idx / Lw, j = idx - r*Lw;
        sStrip[r*LWpad + j] = A[(kb + sPerm[r])*SA + ke + j];
    }
    __syncthreads();

    // U12 = L11^{-1} * strip : independent per-column forward substitution
    for (int j = tid; j < Lw; j += 512) {
        float c[PBW];
        #pragma unroll
        for (int r = 0; r < PBW; r++) c[r] = (r < bw) ? sStrip[r*LWpad + j] : 0.0f;
        #pragma unroll
        for (int r = 1; r < PBW; r++) {
            if (r < bw) {
                float acc = c[r];
                #pragma unroll
                for (int s = 0; s < PBW; s++)
                    if (s < r) acc = fmaf(-sBlk[r][s], c[s], acc);
                c[r] = acc;
            }
        }
        #pragma unroll
        for (int r = 0; r < PBW; r++) if (r < bw) sStrip[r*LWpad + j] = c[r];
    }

    // L21 = A21 * U11^{-1} : independent per-row substitution
    for (int t = tid; t < M; t += 512) {
        float x[PBW];
        float* row = &sA21[t*(PBW+1)];
        #pragma unroll
        for (int j = 0; j < PBW; j++) {
            if (j < bw) {
                float acc = row[j];
                #pragma unroll
                for (int s = 0; s < PBW; s++)
                    if (s < j) acc = fmaf(-x[s], sBlk[s][j], acc);
                x[j] = acc * sInvD[j];
            } else x[j] = 0.0f;
        }
        #pragma unroll
        for (int j = 0; j < PBW; j++) if (j < bw) row[j] = x[j];
    }
    __syncthreads();

    // write back: block (logical order), U12 strip, L21
    for (int idx = tid; idx < bw*bw; idx += 512) {
        int r = idx / bw, j = idx - r*bw;
        A[(kb+r)*SA + kb + j] = sBlk[r][j];
    }
    for (int idx = tid; idx < bw*Lw; idx += 512) {
        int r = idx / Lw, j = idx - r*Lw;
        A[(kb+r)*SA + ke + j] = sStrip[r*LWpad + j];
    }
    for (int idx = tid; idx < M*PBW; idx += 512) {
        int r = idx >> 5, j = idx & 31;
        if (j < bw) A[(ke+r)*SA + kb + j] = sA21[r*(PBW+1) + j];
    }
}

// ============================================================
// Kernel 4: trailing GEMM  A22 -= L21 @ U12   (64x64 tiles, k=32)
// ============================================================
__global__ void __launch_bounds__(256) k_gemm(int kb)
{
    const int ke = kb + PBW;
    const int M = NA - ke, Ncols = 405 - ke;
    const int n = blockIdx.z;
    const int i0 = blockIdx.y * 64;
    const int cb = blockIdx.x * 64;
    const int c0 = ke + cb;
    const int tid = threadIdx.x;
    float* A = &g_A[n][0][0];

    __shared__ float sL[64][PBW+1];
    __shared__ __align__(16) float sU[PBW][68];

    for (int idx = tid; idx < 64*PBW; idx += 256) {
        int r = idx >> 5, kk = idx & 31;
        sL[r][kk] = (i0 + r < M) ? A[(ke+i0+r)*SA + kb + kk] : 0.0f;
    }
    for (int idx = tid; idx < PBW*64; idx += 256) {
        int kk = idx >> 6, c = idx & 63;
        sU[kk][c] = (cb + c < Ncols) ? A[(kb+kk)*SA + c0 + c] : 0.0f;
    }
    __syncthreads();

    const int tx = tid & 15, ty = tid >> 4;
    const int c4 = c0 + tx*4;            // 16B aligned
    const bool colok = (c4 < 405);       // pad cols 405..407 are writable scratch

    float4 acc[4];
    bool rowok[4];
    #pragma unroll
    for (int i = 0; i < 4; i++) {
        int gr = ke + i0 + ty*4 + i;
        rowok[i] = (gr < NA);
        acc[i] = (rowok[i] && colok) ? *(const float4*)&A[gr*SA + c4]
                                     : make_float4(0,0,0,0);
    }
    #pragma unroll
    for (int kk = 0; kk < PBW; kk++) {
        float4 u = *(const float4*)&sU[kk][tx*4];
        #pragma unroll
        for (int i = 0; i < 4; i++) {
            float l = sL[ty*4+i][kk];
            acc[i].x = fmaf(-l, u.x, acc[i].x);
            acc[i].y = fmaf(-l, u.y, acc[i].y);
            acc[i].z = fmaf(-l, u.z, acc[i].z);
            acc[i].w = fmaf(-l, u.w, acc[i].w);
        }
    }
    if (colok) {
        #pragma unroll
        for (int i = 0; i < 4; i++) {
            int gr = ke + i0 + ty*4 + i;
            if (rowok[i]) *(float4*)&A[gr*SA + c4] = acc[i];
        }
    }
}

// ============================================================
// Kernel 5: blocked back substitution (warp-systolic 8x8 diag solves)
// ============================================================
__global__ void __launch_bounds__(512, 1) k_backsub()
{
    const int n = blockIdx.x, tid = threadIdx.x;
    float* A = &g_A[n][0][0];
    __shared__ float sR[NA][2];

    for (int i = tid; i < NA; i += 512) {
        sR[i][0] = A[i*SA + 403];
        sR[i][1] = A[i*SA + 404];
    }
    __syncthreads();

    for (int kb = 400; kb >= 0; kb -= 8) {
        int bw = min(8, NA - kb);
        if (tid < 32) {
            int r = tid;
            float d[8] = {0,0,0,0,0,0,0,0};
            float x0 = 0.f, x1 = 0.f;
            if (r < bw) {
                float4 q0 = *(const float4*)&A[(kb+r)*SA + kb];
                float4 q1 = *(const float4*)&A[(kb+r)*SA + kb + 4];
                d[0]=q0.x; d[1]=q0.y; d[2]=q0.z; d[3]=q0.w;
                d[4]=q1.x; d[5]=q1.y; d[6]=q1.z; d[7]=q1.w;
                x0 = sR[kb+r][0]; x1 = sR[kb+r][1];
            }
            #pragma unroll
            for (int k = 7; k >= 0; k--) {
                if (k < bw) {
                    float xk0 = 0.f, xk1 = 0.f;
                    if (r == k) { float iv = 1.0f/d[k]; xk0 = x0*iv; xk1 = x1*iv; }
                    xk0 = __shfl_sync(0xffffffffu, xk0, k);
                    xk1 = __shfl_sync(0xffffffffu, xk1, k);
                    if (r < k)  { x0 -= d[k]*xk0; x1 -= d[k]*xk1; }
                    if (r == k) { x0 = xk0; x1 = xk1; }
                }
            }
            if (r < bw) { sR[kb+r][0] = x0; sR[kb+r][1] = x1; }
        }
        __syncthreads();
        if (tid < kb) {
            float4 q0 = *(const float4*)&A[tid*SA + kb];
            float4 q1 = *(const float4*)&A[tid*SA + kb + 4];
            float u[8] = {q0.x,q0.y,q0.z,q0.w,q1.x,q1.y,q1.z,q1.w};
            float a0 = sR[tid][0], a1 = sR[tid][1];
            #pragma unroll
            for (int s = 0; s < 8; s++) {
                if (s < bw) { a0 -= u[s]*sR[kb+s][0]; a1 -= u[s]*sR[kb+s][1]; }
            }
            sR[tid][0] = a0; sR[tid][1] = a1;
        }
        __syncthreads();
    }

    // pack: pre-scale weights by 0.5*ln2 so eval uses __log2f only
    const float WS = 0.34657359028f;
    if (tid < KC) {
        int a = tid / KG, b = tid % KG;
        int pix = c_ctrl[a]*Wd + c_ctrl[b];
        g_cw[n][tid] = make_float4(g_cx[n*HW+pix], g_cy[n*HW+pix],
                                   sR[tid][0]*WS, sR[tid][1]*WS);
    }
    if (tid >= KC && tid < NA) {
        int r = tid - KC;
        g_aff[n][r*2+0] = sR[tid][0];
        g_aff[n][r*2+1] = sR[tid][1];
    }
}

// ============================================================
// Kernel 6: fused TPS eval (3 FD queries, trimmed) + compose
// ============================================================
__global__ void __launch_bounds__(256) k_eval(float* __restrict__ out)
{
    __shared__ __align__(16) float4 scw[KC];
    __shared__ float saff[6];

    const int bpn = HW/256;
    int n  = blockIdx.x / bpn;
    int p  = (blockIdx.x - n*bpn)*256 + threadIdx.x;

    for (int i = threadIdx.x; i < KC; i += 256) scw[i] = g_cw[n][i];
    if (threadIdx.x < 6) saff[threadIdx.x] = g_aff[n][threadIdx.x];
    __syncthreads();

    int gi = n*HW + p;
    float qx = g_cx[gi], qy = g_cy[gi];
    float m  = g_m[gi];

    const float DX   = STEPc;
    const float DX2e = DX*DX + EPSc;
    const float TDX  = 2.0f*DX;

    float a00=0.f, a01=0.f, ax0=0.f, ax1=0.f, ay0=0.f, ay1=0.f;

    #pragma unroll 4
    for (int c = 0; c < KC; c++) {
        float4 cw = scw[c];
        float ddx = qx - cw.x;
        float ddy = qy - cw.y;
        float r2   = fmaf(ddx, ddx, ddy*ddy);
        float r2e  = r2 + EPSc;
        float r2pd = r2 + DX2e;
        float r2x  = fmaf(TDX, ddx, r2pd);
        float r2y  = fmaf(TDX, ddy, r2pd);
        float u0 = r2e * __log2f(r2e);
        float ux = r2x * __log2f(r2x);
        float uy = r2y * __log2f(r2y);
        a00 = fmaf(u0, cw.z, a00);  a01 = fmaf(u0, cw.w, a01);
        ax0 = fmaf(ux, cw.z, ax0);  ax1 = fmaf(ux, cw.w, ax1);
        ay0 = fmaf(uy, cw.z, ay0);  ay1 = fmaf(uy, cw.w, ay1);
    }

    float qxx = qx + DX, qyy = qy + DX;
    float c00 = a00 + saff[0] + qx *saff[2] + qy *saff[4];
    float c01 = a01 + saff[1] + qx *saff[3] + qy *saff[5];
    float cx0 = ax0 + saff[0] + qxx*saff[2] + qy *saff[4];
    float cx1 = ax1 + saff[1] + qxx*saff[3] + qy *saff[5];
    float cy0 = ay0 + saff[0] + qx *saff[2] + qyy*saff[4];
    float cy1 = ay1 + saff[1] + qx *saff[3] + qyy*saff[5];

    const float invDX = 1.0f/STEPc;
    float av = (cx0 - c00)*invDX;
    float bv = (cx1 - c01)*invDX;
    float cv = (cy0 - c00)*invDX;
    float dv = (cy1 - c01)*invDX;

    float d0 = g_dx[gi], d1 = g_dy[gi];
    float dn0 = av*d0 + cv*d1;
    float dn1 = bv*d0 + dv*d1;

    int w = p % Wd, h = p / Wd;
    float bx = w*STEPc - 1.0f;
    float by = h*STEPc - 1.0f;
    float o0 = (bx + dn0)*m - 2.0f*(1.0f - m);
    float o1 = (by + dn1)*m - 2.0f*(1.0f - m);
    out[gi*2+0] = o0;
    out[gi*2+1] = o1;
}

// ============================================================
extern "C" void kernel_launch(void* const* d_in, const int* in_sizes, int n_in,
                              void* d_out, int out_size)
{
    const float* in0 = (const float*)d_in[0];
    const float* in1 = (const float*)d_in[1];
    const float* duv;
    const float* uv;
    if (in_sizes[0] == 2*HW) { duv = in0; uv = in1; }
    else                     { duv = in1; uv = in0; }

    float* out = (float*)d_out;
    float* out_mask = out + (size_t)Nb*HW*2;

    const int FSMEM = (PBW*LWpad + 371*(PBW+1)) * 4;   // ~97 KB
    cudaFuncSetAttribute(k_factor, cudaFuncAttributeMaxDynamicSharedMemorySize, FSMEM);

    k_prepare<<<(Nb*HW + 255)/256, 256>>>(duv, uv, out_mask);
    k_build<<<(Nb*NA*SA + 255)/256, 256>>>();

    for (int pan = 0; pan < NPAN; pan++) {
        int kb = pan*PBW;
        int bw = (NA - kb < PBW) ? (NA - kb) : PBW;
        k_factor<<<Nb, 512, FSMEM>>>(kb, bw);
        int ke = kb + bw;
        int M = NA - ke, Ncols = 405 - ke;
        if (M > 0) {
            dim3 grid((Ncols + 63)/64, (M + 63)/64, Nb);
            k_gemm<<<grid, 256>>>(kb);
        }
    }

    k_backsub<<<Nb, 512>>>();
    k_eval<<<Nb*(HW/256), 256>>>(out);
}

// round 11
// speedup vs baseline: 3.0196x; 1.3300x over previous
#include <cuda_runtime.h>
#include <cooperative_groups.h>

namespace cg = cooperative_groups;

#define Hh 192
#define Wd 192
#define HW (Hh*Wd)
#define Nb 6
#define KG 20
#define KC 400
#define NA 403          // 400 ctrl + 3 affine
#define SA 408          // padded row stride (403,404 = rhs, 405..407 pad)
#define PBW 32          // panel/block width
#define NPAN 13
#define CLU 8           // CTAs per cluster (one cluster per batch)
#define LAMBDc 100.0f
#define BIGc 100000000.0f
#define EPSc 1e-9f
#define STEPc (2.0f/191.0f)

__device__ __constant__ int c_ctrl[KG] =
    {0,10,20,30,40,50,60,70,80,90,101,111,121,131,141,151,161,171,181,191};

// ------- scratch (device globals, no allocs) -------
__device__ float g_cx[Nb*HW];
__device__ float g_cy[Nb*HW];
__device__ float g_dx[Nb*HW];
__device__ float g_dy[Nb*HW];
__device__ float g_m [Nb*HW];
__device__ __align__(16) float g_A[Nb][NA][SA];   // ~3.95 MB, L2 resident
__device__ __align__(16) float4 g_cw[Nb][KC];     // (sx, sy, w0*, w1*) pre-scaled
__device__ float g_aff[Nb][6];

// ============================================================
// Kernel 1: fused analytic-field backward warp
// ============================================================
__global__ void k_prepare(const float* __restrict__ duv,
                          const float* __restrict__ uv,
                          float* __restrict__ out_mask)
{
    int idx = blockIdx.x*blockDim.x + threadIdx.x;
    if (idx >= Nb*HW) return;

    float gx = uv[idx*2+0];
    float gy = uv[idx*2+1];
    float x = (gx + 1.0f)*0.5f*(Wd-1);
    float y = (gy + 1.0f)*0.5f*(Hh-1);
    float x0f = floorf(x), y0f = floorf(y);
    float wx = x - x0f,   wy = y - y0f;
    int x0 = (int)x0f, y0 = (int)y0f;

    float acx=0.f, acy=0.f, adx=0.f, ady=0.f, am=0.f;

    #pragma unroll
    for (int cyi = 0; cyi < 2; cyi++) {
        #pragma unroll
        for (int cxi = 0; cxi < 2; cxi++) {
            int xi = x0 + cxi, yi = y0 + cyi;
            float w = (cxi ? wx : 1.0f-wx) * (cyi ? wy : 1.0f-wy);
            if (xi >= 0 && xi < Wd && yi >= 0 && yi < Hh) {
                float du0 = duv[(yi*Wd+xi)*2+0];
                float du1 = duv[(yi*Wd+xi)*2+1];
                float vpix = (fabsf(du0) <= 1.0f && fabsf(du1) <= 1.0f) ? 1.0f : 0.0f;
                float bx = xi*STEPc - 1.0f;
                float by = yi*STEPc - 1.0f;
                acx += w*bx;
                acy += w*by;
                adx += w*(du0-bx)*vpix;
                ady += w*(du1-by)*vpix;
                am  += w*vpix;
            }
        }
    }
    float mth = (am > 0.5f) ? 1.0f : 0.0f;
    g_cx[idx]=acx; g_cy[idx]=acy; g_dx[idx]=adx; g_dy[idx]=ady; g_m[idx]=mth;
    out_mask[idx] = mth;
}

// ============================================================
// Kernel 2: ONE launch — build + blocked LU + back-sub.
// grid = Nb*CLU CTAs, cluster (CLU,1,1): one cluster per batch.
// cluster.sync() (cooperative_groups) carries the acq_rel cluster fence,
// so ptxas emits CCTL.IVALL → peer-CTA global writes are L1-coherent.
// ============================================================
__global__ void __launch_bounds__(512, 1) __cluster_dims__(CLU, 1, 1)
k_lu()
{
    cg::cluster_group cluster = cg::this_cluster();

    const int n    = blockIdx.x / CLU;
    const int rank = blockIdx.x % CLU;
    const int tid  = threadIdx.x;
    const int lane = tid & 31;
    const int wid  = tid >> 5;
    float* A = &g_A[n][0][0];

    __shared__ float  sBlk[PBW][PBW+1];          // L\U block (logical order)
    __shared__ float  sInvD[PBW];
    __shared__ int    sPerm[PBW];
    __shared__ float2 sSrc[KC];
    __shared__ float  sM[KC];
    __shared__ float  sL[64][PBW+1];             // GEMM L21 tile
    __shared__ __align__(16) float sU[PBW][68];  // GEMM U12 tile
    __shared__ float  sR[NA][2];                 // back-sub rhs

    // ---------- build augmented matrix (rows i == rank mod CLU) ----------
    for (int i = tid; i < KC; i += 512) {
        int pix = c_ctrl[i/KG]*Wd + c_ctrl[i%KG];
        sSrc[i] = make_float2(g_cx[n*HW+pix], g_cy[n*HW+pix]);
        sM[i]   = g_m[n*HW+pix];
    }
    __syncthreads();
    for (int i = rank; i < NA; i += CLU) {
        for (int j = tid; j < SA; j += 512) {
            float v = 0.0f;
            if (j < 405) {
                if (i < KC) {
                    float2 si = sSrc[i];
                    if (j < KC) {
                        float2 sj = sSrc[j];
                        float ddx = si.x - sj.x, ddy = si.y - sj.y;
                        float r2 = ddx*ddx + ddy*ddy;
                        v = 0.5f*r2*__logf(r2 + EPSc);
                        if (i == j) v += LAMBDc + BIGc*(1.0f - sM[i]);
                    } else if (j == 400) v = 1.0f;
                    else if (j == 401) v = si.x;
                    else if (j == 402) v = si.y;
                    else if (j == 403) v = c_ctrl[i%KG]*STEPc - 1.0f;
                    else               v = c_ctrl[i/KG]*STEPc - 1.0f;
                } else {
                    int r = i - KC;
                    if (j < KC) {
                        float2 sj = sSrc[j];
                        v = (r==0) ? 1.0f : ((r==1) ? sj.x : sj.y);
                    }
                }
            }
            A[i*SA + j] = v;
        }
    }
    cluster.sync();

    // ---------- panel loop ----------
    for (int pan = 0; pan < NPAN; pan++) {
        const int kb = pan*PBW;
        const int bw = (NA - kb < PBW) ? (NA - kb) : PBW;
        const int ke = kb + bw;
        const int M  = NA - ke;
        const int Lw = 405 - ke;

        // zero block smem (padded region must be 0 for guard-free chains)
        for (int i = tid; i < PBW*(PBW+1); i += 512) (&sBlk[0][0])[i] = 0.0f;
        if (tid < PBW) { sInvD[tid] = 0.0f; sPerm[tid] = tid; }
        __syncthreads();

        // ---- 32x32 register LU with in-block pivoting (warp 0, replicated
        //      in every CTA — identical deterministic result, no broadcast) ----
        if (wid == 0) {
            float a[PBW];
            #pragma unroll
            for (int j = 0; j < PBW; j++)
                a[j] = (lane < bw && j < bw) ? A[(kb+lane)*SA + kb + j] : 0.0f;
            bool mydone = (lane >= bw);
            int myslot = -1;
            #pragma unroll
            for (int s = 0; s < PBW; s++) {
                if (s < bw) {
                    float v = mydone ? 0.0f : fabsf(a[s]);
                    unsigned key = mydone ? 0u
                        : ((__float_as_uint(v) & 0xFFFFFFE0u) | (unsigned)lane);
                    unsigned kmax = __reduce_max_sync(0xffffffffu, key);
                    int p = (int)(kmax & 31u);
                    float piv = __shfl_sync(0xffffffffu, a[s], p);
                    float inv = 1.0f / piv;
                    if (lane == p) { mydone = true; myslot = s; sPerm[s] = lane; sInvD[s] = inv; }
                    float f = mydone ? 0.0f : a[s]*inv;
                    if (!mydone) a[s] = f;
                    #pragma unroll
                    for (int j = 0; j < PBW; j++) {
                        if (j > s) {
                            float u = __shfl_sync(0xffffffffu, a[j], p);
                            if (!mydone) a[j] = fmaf(-f, u, a[j]);
                        }
                    }
                }
            }
            if (myslot >= 0) {
                #pragma unroll
                for (int j = 0; j < PBW; j++) sBlk[myslot][j] = a[j];
            }
        }
        __syncthreads();

        // rank 0 writes the factored block back (back-sub needs U11)
        if (rank == 0) {
            for (int idx = tid; idx < bw*bw; idx += 512) {
                int r = idx / bw, j = idx - r*bw;
                A[(kb+r)*SA + kb + j] = sBlk[r][j];
            }
        }

        // ---- U12 = L11^{-1} P A12 : one column per lane, cluster-wide ----
        {
            int gw = rank*16 + wid;            // 0..127 cluster warps
            int j = gw*PBW + lane;
            if (j < Lw) {
                float c[PBW];
                #pragma unroll
                for (int r = 0; r < PBW; r++) {
                    int pr = (r < bw) ? sPerm[r] : 0;
                    c[r] = A[(kb + pr)*SA + ke + j];
                }
                #pragma unroll
                for (int s = 0; s < PBW-1; s++) {
                    #pragma unroll
                    for (int r = s+1; r < PBW; r++)
                        c[r] = fmaf(-sBlk[r][s], c[s], c[r]);
                }
                #pragma unroll
                for (int r = 0; r < PBW; r++)
                    if (r < bw) A[(kb+r)*SA + ke + j] = c[r];
            }
        }

        // ---- L21 = A21 U11^{-1} : one row per thread, cluster-wide ----
        // (only runs when M>0, i.e. bw==32 — no partial-width guards needed)
        {
            int t = rank*512 + tid;
            if (t < M) {
                float row[PBW];
                float* ap = &A[(ke+t)*SA + kb];
                #pragma unroll
                for (int j = 0; j < PBW; j++) row[j] = ap[j];
                #pragma unroll
                for (int s = 0; s < PBW; s++) {
                    float xs = row[s]*sInvD[s];
                    row[s] = xs;
                    #pragma unroll
                    for (int j = s+1; j < PBW; j++)
                        row[j] = fmaf(-xs, sBlk[s][j], row[j]);
                }
                #pragma unroll
                for (int j = 0; j < PBW; j++) ap[j] = row[j];
            }
        }
        cluster.sync();   // TRSM results visible cluster-wide

        // ---- trailing GEMM  A22 -= L21 @ U12  (64x64 tiles, k=32) ----
        if (M > 0) {
            const int nrt = (M + 63) >> 6;
            const int nct = (Lw + 63) >> 6;
            const int ntiles = nrt*nct;
            const int tx = tid & 15, ty = tid >> 4;   // 16x32 thread grid
            for (int tile = rank; tile < ntiles; tile += CLU) {
                int tr = tile / nct, tc = tile - tr*nct;
                int i0 = tr << 6;
                int cb = tc << 6;
                int c0 = ke + cb;
                for (int idx = tid; idx < 64*PBW; idx += 512) {
                    int r = idx >> 5, kk = idx & 31;
                    sL[r][kk] = (i0 + r < M) ? A[(ke+i0+r)*SA + kb + kk] : 0.0f;
                }
                for (int idx = tid; idx < PBW*64; idx += 512) {
                    int kk = idx >> 6, c = idx & 63;
                    sU[kk][c] = (cb + c < Lw) ? A[(kb+kk)*SA + c0 + c] : 0.0f;
                }
                __syncthreads();

                int c4 = c0 + tx*4;
                bool colok = (c4 < 405);          // pad cols 405..407 writable
                float4 acc[2];
                bool rowok[2];
                #pragma unroll
                for (int i = 0; i < 2; i++) {
                    int gr = ke + i0 + ty*2 + i;
                    rowok[i] = (gr < NA);
                    acc[i] = (rowok[i] && colok) ? *(const float4*)&A[gr*SA + c4]
                                                 : make_float4(0,0,0,0);
                }
                #pragma unroll
                for (int kk = 0; kk < PBW; kk++) {
                    float4 u = *(const float4*)&sU[kk][tx*4];
                    #pragma unroll
                    for (int i = 0; i < 2; i++) {
                        float l = sL[ty*2+i][kk];
                        acc[i].x = fmaf(-l, u.x, acc[i].x);
                        acc[i].y = fmaf(-l, u.y, acc[i].y);
                        acc[i].z = fmaf(-l, u.z, acc[i].z);
                        acc[i].w = fmaf(-l, u.w, acc[i].w);
                    }
                }
                if (colok) {
                    #pragma unroll
                    for (int i = 0; i < 2; i++) {
                        int gr = ke + i0 + ty*2 + i;
                        if (rowok[i]) *(float4*)&A[gr*SA + c4] = acc[i];
                    }
                }
                __syncthreads();
            }
        }
        cluster.sync();   // GEMM visible for next panel's LU
    }

    // ---------- back substitution (rank 0 CTA of each cluster) ----------
    if (rank == 0) {
        for (int i = tid; i < NA; i += 512) {
            sR[i][0] = A[i*SA + 403];
            sR[i][1] = A[i*SA + 404];
        }
        __syncthreads();

        for (int kb = 400; kb >= 0; kb -= 8) {
            int bw = min(8, NA - kb);
            if (tid < 32) {
                int r = tid;
                float d[8] = {0,0,0,0,0,0,0,0};
                float x0 = 0.f, x1 = 0.f;
                if (r < bw) {
                    float4 q0 = *(const float4*)&A[(kb+r)*SA + kb];
                    float4 q1 = *(const float4*)&A[(kb+r)*SA + kb + 4];
                    d[0]=q0.x; d[1]=q0.y; d[2]=q0.z; d[3]=q0.w;
                    d[4]=q1.x; d[5]=q1.y; d[6]=q1.z; d[7]=q1.w;
                    x0 = sR[kb+r][0]; x1 = sR[kb+r][1];
                }
                #pragma unroll
                for (int k = 7; k >= 0; k--) {
                    if (k < bw) {
                        float xk0 = 0.f, xk1 = 0.f;
                        if (r == k) { float iv = 1.0f/d[k]; xk0 = x0*iv; xk1 = x1*iv; }
                        xk0 = __shfl_sync(0xffffffffu, xk0, k);
                        xk1 = __shfl_sync(0xffffffffu, xk1, k);
                        if (r < k)  { x0 -= d[k]*xk0; x1 -= d[k]*xk1; }
                        if (r == k) { x0 = xk0; x1 = xk1; }
                    }
                }
                if (r < bw) { sR[kb+r][0] = x0; sR[kb+r][1] = x1; }
            }
            __syncthreads();
            if (tid < kb) {
                float4 q0 = *(const float4*)&A[tid*SA + kb];
                float4 q1 = *(const float4*)&A[tid*SA + kb + 4];
                float u[8] = {q0.x,q0.y,q0.z,q0.w,q1.x,q1.y,q1.z,q1.w};
                float a0 = sR[tid][0], a1 = sR[tid][1];
                #pragma unroll
                for (int s = 0; s < 8; s++) {
                    if (s < bw) { a0 -= u[s]*sR[kb+s][0]; a1 -= u[s]*sR[kb+s][1]; }
                }
                sR[tid][0] = a0; sR[tid][1] = a1;
            }
            __syncthreads();
        }

        // pack: pre-scale weights by 0.5*ln2 so eval uses __log2f only
        const float WS = 0.34657359028f;
        if (tid < KC) {
            float2 s = sSrc[tid];
            g_cw[n][tid] = make_float4(s.x, s.y, sR[tid][0]*WS, sR[tid][1]*WS);
        }
        if (tid >= KC && tid < NA) {
            int r = tid - KC;
            g_aff[n][r*2+0] = sR[tid][0];
            g_aff[n][r*2+1] = sR[tid][1];
        }
    }
}

// ============================================================
// Kernel 3: fused TPS eval (3 FD queries) + compose
// ============================================================
__global__ void __launch_bounds__(256) k_eval(float* __restrict__ out)
{
    __shared__ __align__(16) float4 scw[KC];
    __shared__ float saff[6];

    const int bpn = HW/256;
    int n  = blockIdx.x / bpn;
    int p  = (blockIdx.x - n*bpn)*256 + threadIdx.x;

    for (int i = threadIdx.x; i < KC; i += 256) scw[i] = g_cw[n][i];
    if (threadIdx.x < 6) saff[threadIdx.x] = g_aff[n][threadIdx.x];
    __syncthreads();

    int gi = n*HW + p;
    float qx = g_cx[gi], qy = g_cy[gi];
    float m  = g_m[gi];

    const float DX   = STEPc;
    const float DX2e = DX*DX + EPSc;
    const float TDX  = 2.0f*DX;

    float a00=0.f, a01=0.f, ax0=0.f, ax1=0.f, ay0=0.f, ay1=0.f;

    #pragma unroll 4
    for (int c = 0; c < KC; c++) {
        float4 cw = scw[c];
        float ddx = qx - cw.x;
        float ddy = qy - cw.y;
        float r2   = fmaf(ddx, ddx, ddy*ddy);
        float r2e  = r2 + EPSc;
        float r2pd = r2 + DX2e;
        float r2x  = fmaf(TDX, ddx, r2pd);
        float r2y  = fmaf(TDX, ddy, r2pd);
        float u0 = r2e * __log2f(r2e);
        float ux = r2x * __log2f(r2x);
        float uy = r2y * __log2f(r2y);
        a00 = fmaf(u0, cw.z, a00);  a01 = fmaf(u0, cw.w, a01);
        ax0 = fmaf(ux, cw.z, ax0);  ax1 = fmaf(ux, cw.w, ax1);
        ay0 = fmaf(uy, cw.z, ay0);  ay1 = fmaf(uy, cw.w, ay1);
    }

    float qxx = qx + DX, qyy = qy + DX;
    float c00 = a00 + saff[0] + qx *saff[2] + qy *saff[4];
    float c01 = a01 + saff[1] + qx *saff[3] + qy *saff[5];
    float cx0 = ax0 + saff[0] + qxx*saff[2] + qy *saff[4];
    float cx1 = ax1 + saff[1] + qxx*saff[3] + qy *saff[5];
    float cy0 = ay0 + saff[0] + qx *saff[2] + qyy*saff[4];
    float cy1 = ay1 + saff[1] + qx *saff[3] + qyy*saff[5];

    const float invDX = 1.0f/STEPc;
    float av = (cx0 - c00)*invDX;
    float bv = (cx1 - c01)*invDX;
    float cv = (cy0 - c00)*invDX;
    float dv = (cy1 - c01)*invDX;

    float d0 = g_dx[gi], d1 = g_dy[gi];
    float dn0 = av*d0 + cv*d1;
    float dn1 = bv*d0 + dv*d1;

    int w = p % Wd, h = p / Wd;
    float bx = w*STEPc - 1.0f;
    float by = h*STEPc - 1.0f;
    float o0 = (bx + dn0)*m - 2.0f*(1.0f - m);
    float o1 = (by + dn1)*m - 2.0f*(1.0f - m);
    out[gi*2+0] = o0;
    out[gi*2+1] = o1;
}

// ============================================================
extern "C" void kernel_launch(void* const* d_in, const int* in_sizes, int n_in,
                              void* d_out, int out_size)
{
    const float* in0 = (const float*)d_in[0];
    const float* in1 = (const float*)d_in[1];
    const float* duv;
    const float* uv;
    if (in_sizes[0] == 2*HW) { duv = in0; uv = in1; }
    else                     { duv = in1; uv = in0; }

    float* out = (float*)d_out;
    float* out_mask = out + (size_t)Nb*HW*2;

    k_prepare<<<(Nb*HW + 255)/256, 256>>>(duv, uv, out_mask);
    k_lu<<<Nb*CLU, 512>>>();
    k_eval<<<Nb*(HW/256), 256>>>(out);
}

// round 12
// speedup vs baseline: 3.2147x; 1.0646x over previous
#include <cuda_runtime.h>
#include <cooperative_groups.h>

namespace cg = cooperative_groups;

#define Hh 192
#define Wd 192
#define HW (Hh*Wd)
#define Nb 6
#define KG 20
#define KC 400
#define NA 403          // 400 ctrl + 3 affine
#define SA 408          // padded row stride (403,404 = rhs, 405..407 pad)
#define PBW 32          // panel/block width
#define NPAN 13
#define CLU 8           // CTAs per cluster (one cluster per batch)
#define LAMBDc 100.0f
#define BIGc 100000000.0f
#define EPSc 1e-9f
#define STEPc (2.0f/191.0f)

#define PACK2(out, lo, hi) \
    asm("mov.b64 %0, {%1, %2};" : "=l"(out) : "f"(lo), "f"(hi))
#define UNPACK2(lo, hi, in) \
    asm("mov.b64 {%0, %1}, %2;" : "=f"(lo), "=f"(hi) : "l"(in))
#define ADD2(out, a, b) \
    asm("add.rn.f32x2 %0, %1, %2;" : "=l"(out) : "l"(a), "l"(b))
#define MUL2(out, a, b) \
    asm("mul.rn.f32x2 %0, %1, %2;" : "=l"(out) : "l"(a), "l"(b))
#define FMA2(out, a, b, c) \
    asm("fma.rn.f32x2 %0, %1, %2, %3;" : "=l"(out) : "l"(a), "l"(b), "l"(c))

__device__ __constant__ int c_ctrl[KG] =
    {0,10,20,30,40,50,60,70,80,90,101,111,121,131,141,151,161,171,181,191};

// ------- scratch (device globals, no allocs) -------
__device__ float g_cx[Nb*HW];
__device__ float g_cy[Nb*HW];
__device__ float g_dx[Nb*HW];
__device__ float g_dy[Nb*HW];
__device__ float g_m [Nb*HW];
__device__ __align__(16) float g_A[Nb][NA][SA];   // ~3.95 MB, L2 resident
__device__ __align__(16) float4 g_cw[Nb][KC];     // (-sx, -sy, w0*WS, w1*WS)
__device__ float g_aff[Nb][6];

// ============================================================
// Kernel 1: fused analytic-field backward warp
// ============================================================
__global__ void k_prepare(const float* __restrict__ duv,
                          const float* __restrict__ uv,
                          float* __restrict__ out_mask)
{
    int idx = blockIdx.x*blockDim.x + threadIdx.x;
    if (idx >= Nb*HW) return;

    float gx = uv[idx*2+0];
    float gy = uv[idx*2+1];
    float x = (gx + 1.0f)*0.5f*(Wd-1);
    float y = (gy + 1.0f)*0.5f*(Hh-1);
    float x0f = floorf(x), y0f = floorf(y);
    float wx = x - x0f,   wy = y - y0f;
    int x0 = (int)x0f, y0 = (int)y0f;

    float acx=0.f, acy=0.f, adx=0.f, ady=0.f, am=0.f;

    #pragma unroll
    for (int cyi = 0; cyi < 2; cyi++) {
        #pragma unroll
        for (int cxi = 0; cxi < 2; cxi++) {
            int xi = x0 + cxi, yi = y0 + cyi;
            float w = (cxi ? wx : 1.0f-wx) * (cyi ? wy : 1.0f-wy);
            if (xi >= 0 && xi < Wd && yi >= 0 && yi < Hh) {
                float du0 = duv[(yi*Wd+xi)*2+0];
                float du1 = duv[(yi*Wd+xi)*2+1];
                float vpix = (fabsf(du0) <= 1.0f && fabsf(du1) <= 1.0f) ? 1.0f : 0.0f;
                float bx = xi*STEPc - 1.0f;
                float by = yi*STEPc - 1.0f;
                acx += w*bx;
                acy += w*by;
                adx += w*(du0-bx)*vpix;
                ady += w*(du1-by)*vpix;
                am  += w*vpix;
            }
        }
    }
    float mth = (am > 0.5f) ? 1.0f : 0.0f;
    g_cx[idx]=acx; g_cy[idx]=acy; g_dx[idx]=adx; g_dy[idx]=ady; g_m[idx]=mth;
    out_mask[idx] = mth;
}

// ============================================================
// Kernel 2: ONE launch — build + blocked LU + back-sub.
// grid = Nb*CLU CTAs, cluster (CLU,1,1): one cluster per batch.
// ============================================================
__global__ void __launch_bounds__(512, 1) __cluster_dims__(CLU, 1, 1)
k_lu()
{
    cg::cluster_group cluster = cg::this_cluster();

    const int n    = blockIdx.x / CLU;
    const int rank = blockIdx.x % CLU;
    const int tid  = threadIdx.x;
    const int lane = tid & 31;
    const int wid  = tid >> 5;
    float* A = &g_A[n][0][0];

    __shared__ float  sBlk[PBW][PBW+1];          // L\U block (logical order)
    __shared__ float  sInvD[PBW];
    __shared__ int    sPerm[PBW];
    __shared__ float2 sSrc[KC];
    __shared__ float  sM[KC];
    __shared__ float  sL[64][PBW+1];             // GEMM L21 tile
    __shared__ __align__(16) float sU[PBW][68];  // GEMM U12 tile
    __shared__ float  sR[NA][2];                 // back-sub rhs

    // ---------- build augmented matrix (rows i == rank mod CLU) ----------
    for (int i = tid; i < KC; i += 512) {
        int pix = c_ctrl[i/KG]*Wd + c_ctrl[i%KG];
        sSrc[i] = make_float2(g_cx[n*HW+pix], g_cy[n*HW+pix]);
        sM[i]   = g_m[n*HW+pix];
    }
    __syncthreads();
    for (int i = rank; i < NA; i += CLU) {
        for (int j = tid; j < SA; j += 512) {
            float v = 0.0f;
            if (j < 405) {
                if (i < KC) {
                    float2 si = sSrc[i];
                    if (j < KC) {
                        float2 sj = sSrc[j];
                        float ddx = si.x - sj.x, ddy = si.y - sj.y;
                        float r2 = ddx*ddx + ddy*ddy;
                        v = 0.5f*r2*__logf(r2 + EPSc);
                        if (i == j) v += LAMBDc + BIGc*(1.0f - sM[i]);
                    } else if (j == 400) v = 1.0f;
                    else if (j == 401) v = si.x;
                    else if (j == 402) v = si.y;
                    else if (j == 403) v = c_ctrl[i%KG]*STEPc - 1.0f;
                    else               v = c_ctrl[i/KG]*STEPc - 1.0f;
                } else {
                    int r = i - KC;
                    if (j < KC) {
                        float2 sj = sSrc[j];
                        v = (r==0) ? 1.0f : ((r==1) ? sj.x : sj.y);
                    }
                }
            }
            A[i*SA + j] = v;
        }
    }
    cluster.sync();

    // ---------- panel loop ----------
    for (int pan = 0; pan < NPAN; pan++) {
        const int kb = pan*PBW;
        const int bw = (NA - kb < PBW) ? (NA - kb) : PBW;
        const int ke = kb + bw;
        const int M  = NA - ke;
        const int Lw = 405 - ke;

        // zero block smem (padded region must be 0 for guard-free chains)
        for (int i = tid; i < PBW*(PBW+1); i += 512) (&sBlk[0][0])[i] = 0.0f;
        if (tid < PBW) { sInvD[tid] = 0.0f; sPerm[tid] = tid; }
        __syncthreads();

        // ---- 32x32 register LU with in-block pivoting (warp 0, replicated
        //      in every CTA — identical deterministic result, no broadcast) ----
        if (wid == 0) {
            float a[PBW];
            #pragma unroll
            for (int j = 0; j < PBW; j++)
                a[j] = (lane < bw && j < bw) ? A[(kb+lane)*SA + kb + j] : 0.0f;
            bool mydone = (lane >= bw);
            int myslot = -1;
            #pragma unroll
            for (int s = 0; s < PBW; s++) {
                if (s < bw) {
                    float v = mydone ? 0.0f : fabsf(a[s]);
                    unsigned key = mydone ? 0u
                        : ((__float_as_uint(v) & 0xFFFFFFE0u) | (unsigned)lane);
                    unsigned kmax = __reduce_max_sync(0xffffffffu, key);
                    int p = (int)(kmax & 31u);
                    float piv = __shfl_sync(0xffffffffu, a[s], p);
                    float inv = 1.0f / piv;
                    if (lane == p) { mydone = true; myslot = s; sPerm[s] = lane; sInvD[s] = inv; }
                    float f = mydone ? 0.0f : a[s]*inv;
                    if (!mydone) a[s] = f;
                    #pragma unroll
                    for (int j = 0; j < PBW; j++) {
                        if (j > s) {
                            float u = __shfl_sync(0xffffffffu, a[j], p);
                            if (!mydone) a[j] = fmaf(-f, u, a[j]);
                        }
                    }
                }
            }
            if (myslot >= 0) {
                #pragma unroll
                for (int j = 0; j < PBW; j++) sBlk[myslot][j] = a[j];
            }
        }
        __syncthreads();

        // rank 0 writes the factored block back (back-sub needs U11)
        if (rank == 0) {
            for (int idx = tid; idx < bw*bw; idx += 512) {
                int r = idx / bw, j = idx - r*bw;
                A[(kb+r)*SA + kb + j] = sBlk[r][j];
            }
        }

        // ---- U12 = L11^{-1} P A12 : one column per lane, INTERLEAVED so
        //      active warp-slots spread across all CLU CTAs ----
        {
            int jb = wid*CLU + rank;           // 0..127 cluster warp slots
            int j = jb*PBW + lane;
            if (j < Lw) {
                float c[PBW];
                #pragma unroll
                for (int r = 0; r < PBW; r++) {
                    int pr = (r < bw) ? sPerm[r] : 0;
                    c[r] = A[(kb + pr)*SA + ke + j];
                }
                #pragma unroll
                for (int s = 0; s < PBW-1; s++) {
                    #pragma unroll
                    for (int r = s+1; r < PBW; r++)
                        c[r] = fmaf(-sBlk[r][s], c[s], c[r]);
                }
                #pragma unroll
                for (int r = 0; r < PBW; r++)
                    if (r < bw) A[(kb+r)*SA + ke + j] = c[r];
            }
        }

        // ---- L21 = A21 U11^{-1} : one row per thread, INTERLEAVED ----
        // (only runs when M>0, i.e. bw==32 — no partial-width guards needed)
        {
            int tb = wid*CLU + rank;
            int t = tb*PBW + lane;
            if (t < M) {
                float row[PBW];
                float* ap = &A[(ke+t)*SA + kb];
                #pragma unroll
                for (int j = 0; j < PBW; j++) row[j] = ap[j];
                #pragma unroll
                for (int s = 0; s < PBW; s++) {
                    float xs = row[s]*sInvD[s];
                    row[s] = xs;
                    #pragma unroll
                    for (int j = s+1; j < PBW; j++)
                        row[j] = fmaf(-xs, sBlk[s][j], row[j]);
                }
                #pragma unroll
                for (int j = 0; j < PBW; j++) ap[j] = row[j];
            }
        }
        cluster.sync();   // TRSM results visible cluster-wide

        // ---- trailing GEMM  A22 -= L21 @ U12  (64x64 tiles, k=32) ----
        if (M > 0) {
            const int nrt = (M + 63) >> 6;
            const int nct = (Lw + 63) >> 6;
            const int ntiles = nrt*nct;
            const int tx = tid & 15, ty = tid >> 4;   // 16x32 thread grid
            for (int tile = rank; tile < ntiles; tile += CLU) {
                int tr = tile / nct, tc = tile - tr*nct;
                int i0 = tr << 6;
                int cb = tc << 6;
                int c0 = ke + cb;
                for (int idx = tid; idx < 64*PBW; idx += 512) {
                    int r = idx >> 5, kk = idx & 31;
                    sL[r][kk] = (i0 + r < M) ? A[(ke+i0+r)*SA + kb + kk] : 0.0f;
                }
                for (int idx = tid; idx < PBW*64; idx += 512) {
                    int kk = idx >> 6, c = idx & 63;
                    sU[kk][c] = (cb + c < Lw) ? A[(kb+kk)*SA + c0 + c] : 0.0f;
                }
                __syncthreads();

                int c4 = c0 + tx*4;
                bool colok = (c4 < 405);          // pad cols 405..407 writable
                float4 acc[2];
                bool rowok[2];
                #pragma unroll
                for (int i = 0; i < 2; i++) {
                    int gr = ke + i0 + ty*2 + i;
                    rowok[i] = (gr < NA);
                    acc[i] = (rowok[i] && colok) ? *(const float4*)&A[gr*SA + c4]
                                                 : make_float4(0,0,0,0);
                }
                #pragma unroll
                for (int kk = 0; kk < PBW; kk++) {
                    float4 u = *(const float4*)&sU[kk][tx*4];
                    #pragma unroll
                    for (int i = 0; i < 2; i++) {
                        float l = sL[ty*2+i][kk];
                        acc[i].x = fmaf(-l, u.x, acc[i].x);
                        acc[i].y = fmaf(-l, u.y, acc[i].y);
                        acc[i].z = fmaf(-l, u.z, acc[i].z);
                        acc[i].w = fmaf(-l, u.w, acc[i].w);
                    }
                }
                if (colok) {
                    #pragma unroll
                    for (int i = 0; i < 2; i++) {
                        int gr = ke + i0 + ty*2 + i;
                        if (rowok[i]) *(float4*)&A[gr*SA + c4] = acc[i];
                    }
                }
                __syncthreads();
            }
        }
        cluster.sync();   // GEMM visible for next panel's LU
    }

    // ---------- back substitution (rank 0 CTA of each cluster) ----------
    if (rank == 0) {
        for (int i = tid; i < NA; i += 512) {
            sR[i][0] = A[i*SA + 403];
            sR[i][1] = A[i*SA + 404];
        }
        __syncthreads();

        for (int kb = 400; kb >= 0; kb -= 8) {
            int bw = min(8, NA - kb);
            if (tid < 32) {
                int r = tid;
                float d[8] = {0,0,0,0,0,0,0,0};
                float x0 = 0.f, x1 = 0.f;
                if (r < bw) {
                    float4 q0 = *(const float4*)&A[(kb+r)*SA + kb];
                    float4 q1 = *(const float4*)&A[(kb+r)*SA + kb + 4];
                    d[0]=q0.x; d[1]=q0.y; d[2]=q0.z; d[3]=q0.w;
                    d[4]=q1.x; d[5]=q1.y; d[6]=q1.z; d[7]=q1.w;
                    x0 = sR[kb+r][0]; x1 = sR[kb+r][1];
                }
                #pragma unroll
                for (int k = 7; k >= 0; k--) {
                    if (k < bw) {
                        float xk0 = 0.f, xk1 = 0.f;
                        if (r == k) { float iv = 1.0f/d[k]; xk0 = x0*iv; xk1 = x1*iv; }
                        xk0 = __shfl_sync(0xffffffffu, xk0, k);
                        xk1 = __shfl_sync(0xffffffffu, xk1, k);
                        if (r < k)  { x0 -= d[k]*xk0; x1 -= d[k]*xk1; }
                        if (r == k) { x0 = xk0; x1 = xk1; }
                    }
                }
                if (r < bw) { sR[kb+r][0] = x0; sR[kb+r][1] = x1; }
            }
            __syncthreads();
            if (tid < kb) {
                float4 q0 = *(const float4*)&A[tid*SA + kb];
                float4 q1 = *(const float4*)&A[tid*SA + kb + 4];
                float u[8] = {q0.x,q0.y,q0.z,q0.w,q1.x,q1.y,q1.z,q1.w};
                float a0 = sR[tid][0], a1 = sR[tid][1];
                #pragma unroll
                for (int s = 0; s < 8; s++) {
                    if (s < bw) { a0 -= u[s]*sR[kb+s][0]; a1 -= u[s]*sR[kb+s][1]; }
                }
                sR[tid][0] = a0; sR[tid][1] = a1;
            }
            __syncthreads();
        }

        // pack for eval: negate src coords, pre-scale weights by 0.5*ln2
        const float WS = 0.34657359028f;
        if (tid < KC) {
            float2 s = sSrc[tid];
            g_cw[n][tid] = make_float4(-s.x, -s.y, sR[tid][0]*WS, sR[tid][1]*WS);
        }
        if (tid >= KC && tid < NA) {
            int r = tid - KC;
            g_aff[n][r*2+0] = sR[tid][0];
            g_aff[n][r*2+1] = sR[tid][1];
        }
    }
}

// ============================================================
// Kernel 3: fused TPS eval (3 FD queries, f32x2-packed) + compose
// ============================================================
__global__ void __launch_bounds__(256) k_eval(float* __restrict__ out)
{
    __shared__ __align__(16) float4 scw[KC];
    __shared__ float saff[6];

    const int bpn = HW/256;
    int n  = blockIdx.x / bpn;
    int p  = (blockIdx.x - n*bpn)*256 + threadIdx.x;

    for (int i = threadIdx.x; i < KC; i += 256) scw[i] = g_cw[n][i];
    if (threadIdx.x < 6) saff[threadIdx.x] = g_aff[n][threadIdx.x];
    __syncthreads();

    int gi = n*HW + p;
    float qx = g_cx[gi], qy = g_cy[gi];
    float m  = g_m[gi];

    const float DX   = STEPc;
    const float DX2e = DX*DX + EPSc;

    unsigned long long qxy, tdx2, eps2;
    PACK2(qxy, qx, qy);
    PACK2(tdx2, 2.0f*DX, 2.0f*DX);
    PACK2(eps2, EPSc, EPSc);
    (void)eps2;

    unsigned long long acc0 = 0ull, accx = 0ull, accy = 0ull;

    const unsigned long long* scw2 = (const unsigned long long*)scw;

    #pragma unroll 4
    for (int c = 0; c < KC; c++) {
        unsigned long long nsxy = scw2[c*2+0];     // (-sx, -sy)
        unsigned long long wzw  = scw2[c*2+1];     // (w0*WS, w1*WS)

        unsigned long long dd;  ADD2(dd, qxy, nsxy);      // (ddx, ddy)
        unsigned long long dd2; MUL2(dd2, dd, dd);
        float dx2v, dy2v; UNPACK2(dx2v, dy2v, dd2);
        float r2  = dx2v + dy2v;
        float r2e = r2 + EPSc;
        float r2pd = r2 + DX2e;
        unsigned long long r2pd2; PACK2(r2pd2, r2pd, r2pd);
        unsigned long long r2xy;  FMA2(r2xy, tdx2, dd, r2pd2);  // (r2x, r2y)
        float r2x, r2y; UNPACK2(r2x, r2y, r2xy);

        float lg0 = __log2f(r2e);
        float lgx = __log2f(r2x);
        float lgy = __log2f(r2y);

        float u0 = r2e * lg0;
        unsigned long long lgxy; PACK2(lgxy, lgx, lgy);
        unsigned long long uxy;  MUL2(uxy, r2xy, lgxy);   // (ux, uy)
        float ux, uy; UNPACK2(ux, uy, uxy);

        unsigned long long u02, ux2, uy2;
        PACK2(u02, u0, u0);
        PACK2(ux2, ux, ux);
        PACK2(uy2, uy, uy);
        FMA2(acc0, u02, wzw, acc0);
        FMA2(accx, ux2, wzw, accx);
        FMA2(accy, uy2, wzw, accy);
    }

    float a00, a01, ax0, ax1, ay0, ay1;
    UNPACK2(a00, a01, acc0);
    UNPACK2(ax0, ax1, accx);
    UNPACK2(ay0, ay1, accy);

    float qxx = qx + DX, qyy = qy + DX;
    float c00 = a00 + saff[0] + qx *saff[2] + qy *saff[4];
    float c01 = a01 + saff[1] + qx *saff[3] + qy *saff[5];
    float cx0 = ax0 + saff[0] + qxx*saff[2] + qy *saff[4];
    float cx1 = ax1 + saff[1] + qxx*saff[3] + qy *saff[5];
    float cy0 = ay0 + saff[0] + qx *saff[2] + qyy*saff[4];
    float cy1 = ay1 + saff[1] + qx *saff[3] + qyy*saff[5];

    const float invDX = 1.0f/STEPc;
    float av = (cx0 - c00)*invDX;
    float bv = (cx1 - c01)*invDX;
    float cv = (cy0 - c00)*invDX;
    float dv = (cy1 - c01)*invDX;

    float d0 = g_dx[gi], d1 = g_dy[gi];
    float dn0 = av*d0 + cv*d1;
    float dn1 = bv*d0 + dv*d1;

    int w = p % Wd, h = p / Wd;
    float bx = w*STEPc - 1.0f;
    float by = h*STEPc - 1.0f;
    float o0 = (bx + dn0)*m - 2.0f*(1.0f - m);
    float o1 = (by + dn1)*m - 2.0f*(1.0f - m);
    out[gi*2+0] = o0;
    out[gi*2+1] = o1;
}

// ============================================================
extern "C" void kernel_launch(void* const* d_in, const int* in_sizes, int n_in,
                              void* d_out, int out_size)
{
    const float* in0 = (const float*)d_in[0];
    const float* in1 = (const float*)d_in[1];
    const float* duv;
    const float* uv;
    if (in_sizes[0] == 2*HW) { duv = in0; uv = in1; }
    else                     { duv = in1; uv = in0; }

    float* out = (float*)d_out;
    float* out_mask = out + (size_t)Nb*HW*2;

    k_prepare<<<(Nb*HW + 255)/256, 256>>>(duv, uv, out_mask);
    k_lu<<<Nb*CLU, 512>>>();
    k_eval<<<Nb*(HW/256), 256>>>(out);
}

// round 13
// speedup vs baseline: 3.6271x; 1.1283x over previous
#include <cuda_runtime.h>
#include <cooperative_groups.h>

namespace cg = cooperative_groups;

#define Hh 192
#define Wd 192
#define HW (Hh*Wd)
#define Nb 6
#define KG 20
#define KC 400
#define NA 403          // 400 ctrl + 3 affine
#define SA 408          // padded row stride (403,404 = rhs, 405..407 pad)
#define PBW 32          // panel/block width
#define NPAN 13
#define CLU 8           // CTAs per cluster (one cluster per batch)
#define LAMBDc 100.0f
#define BIGc 100000000.0f
#define EPSc 1e-9f
#define STEPc (2.0f/191.0f)

#define PACK2(out, lo, hi) \
    asm("mov.b64 %0, {%1, %2};" : "=l"(out) : "f"(lo), "f"(hi))
#define UNPACK2(lo, hi, in) \
    asm("mov.b64 {%0, %1}, %2;" : "=f"(lo), "=f"(hi) : "l"(in))
#define ADD2(out, a, b) \
    asm("add.rn.f32x2 %0, %1, %2;" : "=l"(out) : "l"(a), "l"(b))
#define MUL2(out, a, b) \
    asm("mul.rn.f32x2 %0, %1, %2;" : "=l"(out) : "l"(a), "l"(b))
#define FMA2(out, a, b, c) \
    asm("fma.rn.f32x2 %0, %1, %2, %3;" : "=l"(out) : "l"(a), "l"(b), "l"(c))

__device__ __constant__ int c_ctrl[KG] =
    {0,10,20,30,40,50,60,70,80,90,101,111,121,131,141,151,161,171,181,191};

// ------- scratch (device globals, no allocs) -------
__device__ float g_cx[Nb*HW];
__device__ float g_cy[Nb*HW];
__device__ float g_dx[Nb*HW];
__device__ float g_dy[Nb*HW];
__device__ float g_m [Nb*HW];
__device__ __align__(16) float g_A[Nb][NA][SA];   // ~3.95 MB, L2 resident
__device__ __align__(16) float4 g_cw[Nb][KC];     // (-sx, -sy, w0*WS, w1*WS)
__device__ float g_aff[Nb][6];

// ============================================================
// Kernel 1: fused analytic-field backward warp
// ============================================================
__global__ void k_prepare(const float* __restrict__ duv,
                          const float* __restrict__ uv,
                          float* __restrict__ out_mask)
{
    int idx = blockIdx.x*blockDim.x + threadIdx.x;
    if (idx >= Nb*HW) return;

    float gx = uv[idx*2+0];
    float gy = uv[idx*2+1];
    float x = (gx + 1.0f)*0.5f*(Wd-1);
    float y = (gy + 1.0f)*0.5f*(Hh-1);
    float x0f = floorf(x), y0f = floorf(y);
    float wx = x - x0f,   wy = y - y0f;
    int x0 = (int)x0f, y0 = (int)y0f;

    float acx=0.f, acy=0.f, adx=0.f, ady=0.f, am=0.f;

    #pragma unroll
    for (int cyi = 0; cyi < 2; cyi++) {
        #pragma unroll
        for (int cxi = 0; cxi < 2; cxi++) {
            int xi = x0 + cxi, yi = y0 + cyi;
            float w = (cxi ? wx : 1.0f-wx) * (cyi ? wy : 1.0f-wy);
            if (xi >= 0 && xi < Wd && yi >= 0 && yi < Hh) {
                float du0 = duv[(yi*Wd+xi)*2+0];
                float du1 = duv[(yi*Wd+xi)*2+1];
                float vpix = (fabsf(du0) <= 1.0f && fabsf(du1) <= 1.0f) ? 1.0f : 0.0f;
                float bx = xi*STEPc - 1.0f;
                float by = yi*STEPc - 1.0f;
                acx += w*bx;
                acy += w*by;
                adx += w*(du0-bx)*vpix;
                ady += w*(du1-by)*vpix;
                am  += w*vpix;
            }
        }
    }
    float mth = (am > 0.5f) ? 1.0f : 0.0f;
    g_cx[idx]=acx; g_cy[idx]=acy; g_dx[idx]=adx; g_dy[idx]=ady; g_m[idx]=mth;
    out_mask[idx] = mth;
}

// ============================================================
// Kernel 2: ONE launch — build + blocked LU + back-sub.
// grid = Nb*CLU CTAs, cluster (CLU,1,1): one cluster per batch.
// ============================================================
__global__ void __launch_bounds__(512, 1) __cluster_dims__(CLU, 1, 1)
k_lu()
{
    cg::cluster_group cluster = cg::this_cluster();

    const int n    = blockIdx.x / CLU;
    const int rank = blockIdx.x % CLU;
    const int tid  = threadIdx.x;
    const int lane = tid & 31;
    const int wid  = tid >> 5;
    float* A = &g_A[n][0][0];

    __shared__ float  sBlk[PBW][PBW+1];          // L\U block (logical order)
    __shared__ float  sInvD[PBW];
    __shared__ int    sPerm[PBW];
    __shared__ float2 sSrc[KC];
    __shared__ float  sM[KC];
    __shared__ __align__(16) float sLt[PBW][132];   // GEMM L21 tile, kk-major
    __shared__ __align__(16) float sU[PBW][68];     // GEMM U12 tile
    __shared__ float  sR[NA][2];                 // back-sub rhs
    __shared__ float  sX[PBW][2];                // back-sub block solution

    // ---------- build augmented matrix (rows i == rank mod CLU) ----------
    for (int i = tid; i < KC; i += 512) {
        int pix = c_ctrl[i/KG]*Wd + c_ctrl[i%KG];
        sSrc[i] = make_float2(g_cx[n*HW+pix], g_cy[n*HW+pix]);
        sM[i]   = g_m[n*HW+pix];
    }
    __syncthreads();
    for (int i = rank; i < NA; i += CLU) {
        for (int j = tid; j < SA; j += 512) {
            float v = 0.0f;
            if (j < 405) {
                if (i < KC) {
                    float2 si = sSrc[i];
                    if (j < KC) {
                        float2 sj = sSrc[j];
                        float ddx = si.x - sj.x, ddy = si.y - sj.y;
                        float r2 = ddx*ddx + ddy*ddy;
                        v = 0.5f*r2*__logf(r2 + EPSc);
                        if (i == j) v += LAMBDc + BIGc*(1.0f - sM[i]);
                    } else if (j == 400) v = 1.0f;
                    else if (j == 401) v = si.x;
                    else if (j == 402) v = si.y;
                    else if (j == 403) v = c_ctrl[i%KG]*STEPc - 1.0f;
                    else               v = c_ctrl[i/KG]*STEPc - 1.0f;
                } else {
                    int r = i - KC;
                    if (j < KC) {
                        float2 sj = sSrc[j];
                        v = (r==0) ? 1.0f : ((r==1) ? sj.x : sj.y);
                    }
                }
            }
            A[i*SA + j] = v;
        }
    }
    cluster.sync();

    // ---------- panel loop ----------
    for (int pan = 0; pan < NPAN; pan++) {
        const int kb = pan*PBW;
        const int bw = (NA - kb < PBW) ? (NA - kb) : PBW;
        const int ke = kb + bw;
        const int M  = NA - ke;
        const int Lw = 405 - ke;

        // zero block smem (padded region must be 0 for guard-free chains)
        for (int i = tid; i < PBW*(PBW+1); i += 512) (&sBlk[0][0])[i] = 0.0f;
        if (tid < PBW) { sInvD[tid] = 0.0f; sPerm[tid] = tid; }
        __syncthreads();

        // ---- 32x32 register LU with in-block pivoting (warp 0, replicated
        //      in every CTA — identical deterministic result, no broadcast) ----
        if (wid == 0) {
            float a[PBW];
            #pragma unroll
            for (int j = 0; j < PBW; j++)
                a[j] = (lane < bw && j < bw) ? A[(kb+lane)*SA + kb + j] : 0.0f;
            bool mydone = (lane >= bw);
            int myslot = -1;
            #pragma unroll
            for (int s = 0; s < PBW; s++) {
                if (s < bw) {
                    float v = mydone ? 0.0f : fabsf(a[s]);
                    unsigned key = mydone ? 0u
                        : ((__float_as_uint(v) & 0xFFFFFFE0u) | (unsigned)lane);
                    unsigned kmax = __reduce_max_sync(0xffffffffu, key);
                    int p = (int)(kmax & 31u);
                    float piv = __shfl_sync(0xffffffffu, a[s], p);
                    float inv = 1.0f / piv;
                    if (lane == p) { mydone = true; myslot = s; sPerm[s] = lane; sInvD[s] = inv; }
                    float f = mydone ? 0.0f : a[s]*inv;
                    if (!mydone) a[s] = f;
                    #pragma unroll
                    for (int j = 0; j < PBW; j++) {
                        if (j > s) {
                            float u = __shfl_sync(0xffffffffu, a[j], p);
                            if (!mydone) a[j] = fmaf(-f, u, a[j]);
                        }
                    }
                }
            }
            if (myslot >= 0) {
                #pragma unroll
                for (int j = 0; j < PBW; j++) sBlk[myslot][j] = a[j];
            }
        }
        __syncthreads();

        // rank 0 writes the factored block back (back-sub needs U11)
        if (rank == 0) {
            for (int idx = tid; idx < bw*bw; idx += 512) {
                int r = idx / bw, j = idx - r*bw;
                A[(kb+r)*SA + kb + j] = sBlk[r][j];
            }
        }

        // ---- U12 = L11^{-1} P A12 : one column per lane, INTERLEAVED so
        //      active warp-slots spread across all CLU CTAs ----
        {
            int jb = wid*CLU + rank;           // 0..127 cluster warp slots
            int j = jb*PBW + lane;
            if (j < Lw) {
                float c[PBW];
                #pragma unroll
                for (int r = 0; r < PBW; r++) {
                    int pr = (r < bw) ? sPerm[r] : 0;
                    c[r] = A[(kb + pr)*SA + ke + j];
                }
                #pragma unroll
                for (int s = 0; s < PBW-1; s++) {
                    #pragma unroll
                    for (int r = s+1; r < PBW; r++)
                        c[r] = fmaf(-sBlk[r][s], c[s], c[r]);
                }
                #pragma unroll
                for (int r = 0; r < PBW; r++)
                    if (r < bw) A[(kb+r)*SA + ke + j] = c[r];
            }
        }

        // ---- L21 = A21 U11^{-1} : one row per thread, INTERLEAVED ----
        // (only runs when M>0, i.e. bw==32 — no partial-width guards needed)
        {
            int tb = wid*CLU + rank;
            int t = tb*PBW + lane;
            if (t < M) {
                float row[PBW];
                float* ap = &A[(ke+t)*SA + kb];
                #pragma unroll
                for (int j = 0; j < PBW; j++) row[j] = ap[j];
                #pragma unroll
                for (int s = 0; s < PBW; s++) {
                    float xs = row[s]*sInvD[s];
                    row[s] = xs;
                    #pragma unroll
                    for (int j = s+1; j < PBW; j++)
                        row[j] = fmaf(-xs, sBlk[s][j], row[j]);
                }
                #pragma unroll
                for (int j = 0; j < PBW; j++) ap[j] = row[j];
            }
        }
        cluster.sync();   // TRSM results visible cluster-wide

        // ---- trailing GEMM  A22 -= L21 @ U12  (128x64 tiles, k=32) ----
        if (M > 0) {
            const int nrt = (M + 127) >> 7;
            const int nct = (Lw + 63) >> 6;
            const int ntiles = nrt*nct;
            const int tx = tid & 15, ty = tid >> 4;   // 16 x 32 thread grid
            for (int tile = rank; tile < ntiles; tile += CLU) {
                int tr = tile / nct, tc = tile - tr*nct;
                int i0 = tr << 7;
                int cb = tc << 6;
                int c0 = ke + cb;
                // load L (kk-major transpose: coalesced global, aligned LDS.128)
                for (int idx = tid; idx < 128*PBW; idx += 512) {
                    int r = idx >> 5, kk = idx & 31;
                    sLt[kk][r] = (i0 + r < M) ? A[(ke+i0+r)*SA + kb + kk] : 0.0f;
                }
                for (int idx = tid; idx < PBW*64; idx += 512) {
                    int kk = idx >> 6, c = idx & 63;
                    sU[kk][c] = (cb + c < Lw) ? A[(kb+kk)*SA + c0 + c] : 0.0f;
                }
                __syncthreads();

                int c4 = c0 + tx*4;
                bool colok = (c4 < 405);          // pad cols 405..407 writable
                float4 acc[4];
                bool rowok[4];
                #pragma unroll
                for (int i = 0; i < 4; i++) {
                    int gr = ke + i0 + ty*4 + i;
                    rowok[i] = (gr < NA);
                    acc[i] = (rowok[i] && colok) ? *(const float4*)&A[gr*SA + c4]
                                                 : make_float4(0,0,0,0);
                }
                #pragma unroll
                for (int kk = 0; kk < PBW; kk++) {
                    float4 u = *(const float4*)&sU[kk][tx*4];
                    float4 l = *(const float4*)&sLt[kk][ty*4];
                    float lv[4] = {l.x, l.y, l.z, l.w};
                    #pragma unroll
                    for (int i = 0; i < 4; i++) {
                        acc[i].x = fmaf(-lv[i], u.x, acc[i].x);
                        acc[i].y = fmaf(-lv[i], u.y, acc[i].y);
                        acc[i].z = fmaf(-lv[i], u.z, acc[i].z);
                        acc[i].w = fmaf(-lv[i], u.w, acc[i].w);
                    }
                }
                if (colok) {
                    #pragma unroll
                    for (int i = 0; i < 4; i++) {
                        int gr = ke + i0 + ty*4 + i;
                        if (rowok[i]) *(float4*)&A[gr*SA + c4] = acc[i];
                    }
                }
                __syncthreads();
            }
        }
        cluster.sync();   // GEMM visible for next panel's LU
    }

    // ---------- back substitution: 32-wide warp-systolic blocks (rank 0) ----------
    if (rank == 0) {
        for (int i = tid; i < NA; i += 512) {
            sR[i][0] = A[i*SA + 403];
            sR[i][1] = A[i*SA + 404];
        }
        __syncthreads();

        for (int kbb = (NPAN-1)*PBW; kbb >= 0; kbb -= PBW) {
            int nact = NA - kbb; if (nact > PBW) nact = PBW;   // 19 then 32s
            if (wid == 0) {
                // lane r holds row (kbb+r) of the U diag block; identity-pad
                float t[PBW];
                float x0 = 0.f, x1 = 0.f;
                int gr = kbb + lane;
                bool rok = (lane < nact);
                #pragma unroll
                for (int j = 0; j < PBW; j++) {
                    bool ok = rok && (j < nact);
                    t[j] = ok ? A[gr*SA + kbb + j] : ((j == lane) ? 1.0f : 0.0f);
                }
                if (rok) { x0 = sR[gr][0]; x1 = sR[gr][1]; }
                #pragma unroll
                for (int k = PBW-1; k >= 0; k--) {
                    float xk0 = 0.f, xk1 = 0.f;
                    if (lane == k) {
                        float iv = 1.0f / t[k];
                        xk0 = x0*iv; xk1 = x1*iv;
                        x0 = xk0; x1 = xk1;
                    }
                    xk0 = __shfl_sync(0xffffffffu, xk0, k);
                    xk1 = __shfl_sync(0xffffffffu, xk1, k);
                    if (lane < k) {
                        x0 = fmaf(-t[k], xk0, x0);
                        x1 = fmaf(-t[k], xk1, x1);
                    }
                }
                if (rok) { sR[gr][0] = x0; sR[gr][1] = x1; }
                sX[lane][0] = rok ? x0 : 0.0f;
                sX[lane][1] = rok ? x1 : 0.0f;
            }
            __syncthreads();
            // rank-32 update of rows above (sX zero-padded → unguarded j loop;
            // stray cols 403/404 reads are finite rhs values multiplied by 0)
            for (int i = tid; i < kbb; i += 512) {
                const float* ap = &A[i*SA + kbb];
                float a0 = sR[i][0], a1 = sR[i][1];
                #pragma unroll
                for (int j = 0; j < PBW; j++) {
                    float u = ap[j];
                    a0 = fmaf(-u, sX[j][0], a0);
                    a1 = fmaf(-u, sX[j][1], a1);
                }
                sR[i][0] = a0; sR[i][1] = a1;
            }
            __syncthreads();
        }

        // pack for eval: negate src coords, pre-scale weights by 0.5*ln2
        const float WS = 0.34657359028f;
        if (tid < KC) {
            float2 s = sSrc[tid];
            g_cw[n][tid] = make_float4(-s.x, -s.y, sR[tid][0]*WS, sR[tid][1]*WS);
        }
        if (tid >= KC && tid < NA) {
            int r = tid - KC;
            g_aff[n][r*2+0] = sR[tid][0];
            g_aff[n][r*2+1] = sR[tid][1];
        }
    }
}

// ============================================================
// Kernel 3: fused TPS eval (3 FD queries, f32x2-packed) + compose
// ============================================================
__global__ void __launch_bounds__(256) k_eval(float* __restrict__ out)
{
    __shared__ __align__(16) float4 scw[KC];
    __shared__ float saff[6];

    const int bpn = HW/256;
    int n  = blockIdx.x / bpn;
    int p  = (blockIdx.x - n*bpn)*256 + threadIdx.x;

    for (int i = threadIdx.x; i < KC; i += 256) scw[i] = g_cw[n][i];
    if (threadIdx.x < 6) saff[threadIdx.x] = g_aff[n][threadIdx.x];
    __syncthreads();

    int gi = n*HW + p;
    float qx = g_cx[gi], qy = g_cy[gi];
    float m  = g_m[gi];

    const float DX   = STEPc;
    const float DX2e = DX*DX + EPSc;

    unsigned long long qxy, tdx2;
    PACK2(qxy, qx, qy);
    PACK2(tdx2, 2.0f*DX, 2.0f*DX);

    unsigned long long acc0 = 0ull, accx = 0ull, accy = 0ull;

    const unsigned long long* scw2 = (const unsigned long long*)scw;

    #pragma unroll 4
    for (int c = 0; c < KC; c++) {
        unsigned long long nsxy = scw2[c*2+0];     // (-sx, -sy)
        unsigned long long wzw  = scw2[c*2+1];     // (w0*WS, w1*WS)

        unsigned long long dd;  ADD2(dd, qxy, nsxy);      // (ddx, ddy)
        unsigned long long dd2; MUL2(dd2, dd, dd);
        float dx2v, dy2v; UNPACK2(dx2v, dy2v, dd2);
        float r2  = dx2v + dy2v;
        float r2e = r2 + EPSc;
        float r2pd = r2 + DX2e;
        unsigned long long r2pd2; PACK2(r2pd2, r2pd, r2pd);
        unsigned long long r2xy;  FMA2(r2xy, tdx2, dd, r2pd2);  // (r2x, r2y)
        float r2x, r2y; UNPACK2(r2x, r2y, r2xy);

        float lg0 = __log2f(r2e);
        float lgx = __log2f(r2x);
        float lgy = __log2f(r2y);

        float u0 = r2e * lg0;
        unsigned long long lgxy; PACK2(lgxy, lgx, lgy);
        unsigned long long uxy;  MUL2(uxy, r2xy, lgxy);   // (ux, uy)
        float ux, uy; UNPACK2(ux, uy, uxy);

        unsigned long long u02, ux2, uy2;
        PACK2(u02, u0, u0);
        PACK2(ux2, ux, ux);
        PACK2(uy2, uy, uy);
        FMA2(acc0, u02, wzw, acc0);
        FMA2(accx, ux2, wzw, accx);
        FMA2(accy, uy2, wzw, accy);
    }

    float a00, a01, ax0, ax1, ay0, ay1;
    UNPACK2(a00, a01, acc0);
    UNPACK2(ax0, ax1, accx);
    UNPACK2(ay0, ay1, accy);

    float qxx = qx + DX, qyy = qy + DX;
    float c00 = a00 + saff[0] + qx *saff[2] + qy *saff[4];
    float c01 = a01 + saff[1] + qx *saff[3] + qy *saff[5];
    float cx0 = ax0 + saff[0] + qxx*saff[2] + qy *saff[4];
    float cx1 = ax1 + saff[1] + qxx*saff[3] + qy *saff[5];
    float cy0 = ay0 + saff[0] + qx *saff[2] + qyy*saff[4];
    float cy1 = ay1 + saff[1] + qx *saff[3] + qyy*saff[5];

    const float invDX = 1.0f/STEPc;
    float av = (cx0 - c00)*invDX;
    float bv = (cx1 - c01)*invDX;
    float cv = (cy0 - c00)*invDX;
    float dv = (cy1 - c01)*invDX;

    float d0 = g_dx[gi], d1 = g_dy[gi];
    float dn0 = av*d0 + cv*d1;
    float dn1 = bv*d0 + dv*d1;

    int w = p % Wd, h = p / Wd;
    float bx = w*STEPc - 1.0f;
    float by = h*STEPc - 1.0f;
    float o0 = (bx + dn0)*m - 2.0f*(1.0f - m);
    float o1 = (by + dn1)*m - 2.0f*(1.0f - m);
    out[gi*2+0] = o0;
    out[gi*2+1] = o1;
}

// ============================================================
extern "C" void kernel_launch(void* const* d_in, const int* in_sizes, int n_in,
                              void* d_out, int out_size)
{
    const float* in0 = (const float*)d_in[0];
    const float* in1 = (const float*)d_in[1];
    const float* duv;
    const float* uv;
    if (in_sizes[0] == 2*HW) { duv = in0; uv = in1; }
    else                     { duv = in1; uv = in0; }

    float* out = (float*)d_out;
    float* out_mask = out + (size_t)Nb*HW*2;

    k_prepare<<<(Nb*HW + 255)/256, 256>>>(duv, uv, out_mask);
    k_lu<<<Nb*CLU, 512>>>();
    k_eval<<<Nb*(HW/256), 256>>>(out);
}

// round 14
// speedup vs baseline: 4.1580x; 1.1464x over previous
#include <cuda_runtime.h>
#include <cooperative_groups.h>

namespace cg = cooperative_groups;

#define Hh 192
#define Wd 192
#define HW (Hh*Wd)
#define Nb 6
#define KG 20
#define KC 400
#define NA 403          // 400 ctrl + 3 affine
#define SA 408          // padded row stride (403,404 = rhs, 405..407 pad)
#define PBW 32          // panel/block width
#define NPAN 13
#define CLU 8           // CTAs per cluster (one cluster per batch)
#define LAMBDc 100.0f
#define BIGc 100000000.0f
#define EPSc 1e-9f
#define STEPc (2.0f/191.0f)

#define PACK2(out, lo, hi) \
    asm("mov.b64 %0, {%1, %2};" : "=l"(out) : "f"(lo), "f"(hi))
#define UNPACK2(lo, hi, in) \
    asm("mov.b64 {%0, %1}, %2;" : "=f"(lo), "=f"(hi) : "l"(in))
#define ADD2(out, a, b) \
    asm("add.rn.f32x2 %0, %1, %2;" : "=l"(out) : "l"(a), "l"(b))
#define MUL2(out, a, b) \
    asm("mul.rn.f32x2 %0, %1, %2;" : "=l"(out) : "l"(a), "l"(b))
#define FMA2(out, a, b, c) \
    asm("fma.rn.f32x2 %0, %1, %2, %3;" : "=l"(out) : "l"(a), "l"(b), "l"(c))

__device__ __constant__ int c_ctrl[KG] =
    {0,10,20,30,40,50,60,70,80,90,101,111,121,131,141,151,161,171,181,191};

// ------- scratch (device globals, no allocs) -------
__device__ float g_cx[Nb*HW];
__device__ float g_cy[Nb*HW];
__device__ float g_dx[Nb*HW];
__device__ float g_dy[Nb*HW];
__device__ float g_m [Nb*HW];
__device__ __align__(16) float g_A[Nb][NA][SA];   // ~3.95 MB, L2 resident
__device__ __align__(16) float4 g_cw[Nb][KC];     // (-sx, -sy, w0, w1)
__device__ float g_aff[Nb][6];

// ============================================================
// Kernel 1: fused analytic-field backward warp
// ============================================================
__global__ void k_prepare(const float* __restrict__ duv,
                          const float* __restrict__ uv,
                          float* __restrict__ out_mask)
{
    int idx = blockIdx.x*blockDim.x + threadIdx.x;
    if (idx >= Nb*HW) return;

    float gx = uv[idx*2+0];
    float gy = uv[idx*2+1];
    float x = (gx + 1.0f)*0.5f*(Wd-1);
    float y = (gy + 1.0f)*0.5f*(Hh-1);
    float x0f = floorf(x), y0f = floorf(y);
    float wx = x - x0f,   wy = y - y0f;
    int x0 = (int)x0f, y0 = (int)y0f;

    float acx=0.f, acy=0.f, adx=0.f, ady=0.f, am=0.f;

    #pragma unroll
    for (int cyi = 0; cyi < 2; cyi++) {
        #pragma unroll
        for (int cxi = 0; cxi < 2; cxi++) {
            int xi = x0 + cxi, yi = y0 + cyi;
            float w = (cxi ? wx : 1.0f-wx) * (cyi ? wy : 1.0f-wy);
            if (xi >= 0 && xi < Wd && yi >= 0 && yi < Hh) {
                float du0 = duv[(yi*Wd+xi)*2+0];
                float du1 = duv[(yi*Wd+xi)*2+1];
                float vpix = (fabsf(du0) <= 1.0f && fabsf(du1) <= 1.0f) ? 1.0f : 0.0f;
                float bx = xi*STEPc - 1.0f;
                float by = yi*STEPc - 1.0f;
                acx += w*bx;
                acy += w*by;
                adx += w*(du0-bx)*vpix;
                ady += w*(du1-by)*vpix;
                am  += w*vpix;
            }
        }
    }
    float mth = (am > 0.5f) ? 1.0f : 0.0f;
    g_cx[idx]=acx; g_cy[idx]=acy; g_dx[idx]=adx; g_dy[idx]=ady; g_m[idx]=mth;
    out_mask[idx] = mth;
}

// ============================================================
// Kernel 2: ONE launch — build + blocked LU + back-sub.
// grid = Nb*CLU CTAs, cluster (CLU,1,1): one cluster per batch.
// ============================================================
__global__ void __launch_bounds__(512, 1) __cluster_dims__(CLU, 1, 1)
k_lu()
{
    cg::cluster_group cluster = cg::this_cluster();

    const int n    = blockIdx.x / CLU;
    const int rank = blockIdx.x % CLU;
    const int tid  = threadIdx.x;
    const int lane = tid & 31;
    const int wid  = tid >> 5;
    float* A = &g_A[n][0][0];

    __shared__ float  sBlk[PBW][PBW+1];          // L\U block (logical order)
    __shared__ float  sInvD[PBW];
    __shared__ int    sPerm[PBW];
    __shared__ float2 sSrc[KC];
    __shared__ float  sM[KC];
    __shared__ __align__(16) float sLt[PBW][132];   // GEMM L21 tile, kk-major
    __shared__ __align__(16) float sU[PBW][68];     // GEMM U12 tile
    __shared__ float  sR[NA][2];                 // back-sub rhs
    __shared__ float  sX[PBW][2];                // back-sub block solution

    // ---------- build augmented matrix (rows i == rank mod CLU) ----------
    for (int i = tid; i < KC; i += 512) {
        int pix = c_ctrl[i/KG]*Wd + c_ctrl[i%KG];
        sSrc[i] = make_float2(g_cx[n*HW+pix], g_cy[n*HW+pix]);
        sM[i]   = g_m[n*HW+pix];
    }
    __syncthreads();
    for (int i = rank; i < NA; i += CLU) {
        for (int j = tid; j < SA; j += 512) {
            float v = 0.0f;
            if (j < 405) {
                if (i < KC) {
                    float2 si = sSrc[i];
                    if (j < KC) {
                        float2 sj = sSrc[j];
                        float ddx = si.x - sj.x, ddy = si.y - sj.y;
                        float r2 = ddx*ddx + ddy*ddy;
                        v = 0.5f*r2*__logf(r2 + EPSc);
                        if (i == j) v += LAMBDc + BIGc*(1.0f - sM[i]);
                    } else if (j == 400) v = 1.0f;
                    else if (j == 401) v = si.x;
                    else if (j == 402) v = si.y;
                    else if (j == 403) v = c_ctrl[i%KG]*STEPc - 1.0f;
                    else               v = c_ctrl[i/KG]*STEPc - 1.0f;
                } else {
                    int r = i - KC;
                    if (j < KC) {
                        float2 sj = sSrc[j];
                        v = (r==0) ? 1.0f : ((r==1) ? sj.x : sj.y);
                    }
                }
            }
            A[i*SA + j] = v;
        }
    }
    cluster.sync();

    // ---------- panel loop ----------
    for (int pan = 0; pan < NPAN; pan++) {
        const int kb = pan*PBW;
        const int bw = (NA - kb < PBW) ? (NA - kb) : PBW;
        const int ke = kb + bw;
        const int M  = NA - ke;
        const int Lw = 405 - ke;

        // zero block smem (padded region must be 0 for guard-free chains)
        for (int i = tid; i < PBW*(PBW+1); i += 512) (&sBlk[0][0])[i] = 0.0f;
        if (tid < PBW) { sInvD[tid] = 0.0f; sPerm[tid] = tid; }
        __syncthreads();

        // ---- 32x32 register LU with in-block pivoting (warp 0, replicated
        //      in every CTA — identical deterministic result, no broadcast) ----
        if (wid == 0) {
            float a[PBW];
            #pragma unroll
            for (int j = 0; j < PBW; j++)
                a[j] = (lane < bw && j < bw) ? A[(kb+lane)*SA + kb + j] : 0.0f;
            bool mydone = (lane >= bw);
            int myslot = -1;
            #pragma unroll
            for (int s = 0; s < PBW; s++) {
                if (s < bw) {
                    float v = mydone ? 0.0f : fabsf(a[s]);
                    unsigned key = mydone ? 0u
                        : ((__float_as_uint(v) & 0xFFFFFFE0u) | (unsigned)lane);
                    unsigned kmax = __reduce_max_sync(0xffffffffu, key);
                    int p = (int)(kmax & 31u);
                    float piv = __shfl_sync(0xffffffffu, a[s], p);
                    float inv = 1.0f / piv;
                    if (lane == p) { mydone = true; myslot = s; sPerm[s] = lane; sInvD[s] = inv; }
                    float f = mydone ? 0.0f : a[s]*inv;
                    if (!mydone) a[s] = f;
                    #pragma unroll
                    for (int j = 0; j < PBW; j++) {
                        if (j > s) {
                            float u = __shfl_sync(0xffffffffu, a[j], p);
                            if (!mydone) a[j] = fmaf(-f, u, a[j]);
                        }
                    }
                }
            }
            if (myslot >= 0) {
                #pragma unroll
                for (int j = 0; j < PBW; j++) sBlk[myslot][j] = a[j];
            }
        }
        __syncthreads();

        // rank 0 writes the factored block back (back-sub needs U11)
        if (rank == 0) {
            for (int idx = tid; idx < bw*bw; idx += 512) {
                int r = idx / bw, j = idx - r*bw;
                A[(kb+r)*SA + kb + j] = sBlk[r][j];
            }
        }

        // ---- U12 = L11^{-1} P A12 : one column per lane, INTERLEAVED so
        //      active warp-slots spread across all CLU CTAs ----
        {
            int jb = wid*CLU + rank;           // 0..127 cluster warp slots
            int j = jb*PBW + lane;
            if (j < Lw) {
                float c[PBW];
                #pragma unroll
                for (int r = 0; r < PBW; r++) {
                    int pr = (r < bw) ? sPerm[r] : 0;
                    c[r] = A[(kb + pr)*SA + ke + j];
                }
                #pragma unroll
                for (int s = 0; s < PBW-1; s++) {
                    #pragma unroll
                    for (int r = s+1; r < PBW; r++)
                        c[r] = fmaf(-sBlk[r][s], c[s], c[r]);
                }
                #pragma unroll
                for (int r = 0; r < PBW; r++)
                    if (r < bw) A[(kb+r)*SA + ke + j] = c[r];
            }
        }

        // ---- L21 = A21 U11^{-1} : one row per thread, INTERLEAVED ----
        // (only runs when M>0, i.e. bw==32 — no partial-width guards needed)
        {
            int tb = wid*CLU + rank;
            int t = tb*PBW + lane;
            if (t < M) {
                float row[PBW];
                float* ap = &A[(ke+t)*SA + kb];
                #pragma unroll
                for (int j = 0; j < PBW; j++) row[j] = ap[j];
                #pragma unroll
                for (int s = 0; s < PBW; s++) {
                    float xs = row[s]*sInvD[s];
                    row[s] = xs;
                    #pragma unroll
                    for (int j = s+1; j < PBW; j++)
                        row[j] = fmaf(-xs, sBlk[s][j], row[j]);
                }
                #pragma unroll
                for (int j = 0; j < PBW; j++) ap[j] = row[j];
            }
        }
        cluster.sync();   // TRSM results visible cluster-wide

        // ---- trailing GEMM  A22 -= L21 @ U12  (128x64 tiles, k=32) ----
        if (M > 0) {
            const int nrt = (M + 127) >> 7;
            const int nct = (Lw + 63) >> 6;
            const int ntiles = nrt*nct;
            const int tx = tid & 15, ty = tid >> 4;   // 16 x 32 thread grid
            for (int tile = rank; tile < ntiles; tile += CLU) {
                int tr = tile / nct, tc = tile - tr*nct;
                int i0 = tr << 7;
                int cb = tc << 6;
                int c0 = ke + cb;
                // load L (kk-major transpose: coalesced global, aligned LDS.128)
                for (int idx = tid; idx < 128*PBW; idx += 512) {
                    int r = idx >> 5, kk = idx & 31;
                    sLt[kk][r] = (i0 + r < M) ? A[(ke+i0+r)*SA + kb + kk] : 0.0f;
                }
                for (int idx = tid; idx < PBW*64; idx += 512) {
                    int kk = idx >> 6, c = idx & 63;
                    sU[kk][c] = (cb + c < Lw) ? A[(kb+kk)*SA + c0 + c] : 0.0f;
                }
                __syncthreads();

                int c4 = c0 + tx*4;
                bool colok = (c4 < 405);          // pad cols 405..407 writable
                float4 acc[4];
                bool rowok[4];
                #pragma unroll
                for (int i = 0; i < 4; i++) {
                    int gr = ke + i0 + ty*4 + i;
                    rowok[i] = (gr < NA);
                    acc[i] = (rowok[i] && colok) ? *(const float4*)&A[gr*SA + c4]
                                                 : make_float4(0,0,0,0);
                }
                #pragma unroll
                for (int kk = 0; kk < PBW; kk++) {
                    float4 u = *(const float4*)&sU[kk][tx*4];
                    float4 l = *(const float4*)&sLt[kk][ty*4];
                    float lv[4] = {l.x, l.y, l.z, l.w};
                    #pragma unroll
                    for (int i = 0; i < 4; i++) {
                        acc[i].x = fmaf(-lv[i], u.x, acc[i].x);
                        acc[i].y = fmaf(-lv[i], u.y, acc[i].y);
                        acc[i].z = fmaf(-lv[i], u.z, acc[i].z);
                        acc[i].w = fmaf(-lv[i], u.w, acc[i].w);
                    }
                }
                if (colok) {
                    #pragma unroll
                    for (int i = 0; i < 4; i++) {
                        int gr = ke + i0 + ty*4 + i;
                        if (rowok[i]) *(float4*)&A[gr*SA + c4] = acc[i];
                    }
                }
                __syncthreads();
            }
        }
        cluster.sync();   // GEMM visible for next panel's LU
    }

    // ---------- back substitution: 32-wide warp-systolic blocks (rank 0) ----------
    if (rank == 0) {
        for (int i = tid; i < NA; i += 512) {
            sR[i][0] = A[i*SA + 403];
            sR[i][1] = A[i*SA + 404];
        }
        __syncthreads();

        for (int kbb = (NPAN-1)*PBW; kbb >= 0; kbb -= PBW) {
            int nact = NA - kbb; if (nact > PBW) nact = PBW;   // 19 then 32s
            if (wid == 0) {
                // lane r holds row (kbb+r) of the U diag block; identity-pad
                float t[PBW];
                float x0 = 0.f, x1 = 0.f;
                int gr = kbb + lane;
                bool rok = (lane < nact);
                #pragma unroll
                for (int j = 0; j < PBW; j++) {
                    bool ok = rok && (j < nact);
                    t[j] = ok ? A[gr*SA + kbb + j] : ((j == lane) ? 1.0f : 0.0f);
                }
                if (rok) { x0 = sR[gr][0]; x1 = sR[gr][1]; }
                #pragma unroll
                for (int k = PBW-1; k >= 0; k--) {
                    float xk0 = 0.f, xk1 = 0.f;
                    if (lane == k) {
                        float iv = 1.0f / t[k];
                        xk0 = x0*iv; xk1 = x1*iv;
                        x0 = xk0; x1 = xk1;
                    }
                    xk0 = __shfl_sync(0xffffffffu, xk0, k);
                    xk1 = __shfl_sync(0xffffffffu, xk1, k);
                    if (lane < k) {
                        x0 = fmaf(-t[k], xk0, x0);
                        x1 = fmaf(-t[k], xk1, x1);
                    }
                }
                if (rok) { sR[gr][0] = x0; sR[gr][1] = x1; }
                sX[lane][0] = rok ? x0 : 0.0f;
                sX[lane][1] = rok ? x1 : 0.0f;
            }
            __syncthreads();
            // rank-32 update of rows above (sX zero-padded → unguarded j loop;
            // stray cols 403/404 reads are finite rhs values multiplied by 0)
            for (int i = tid; i < kbb; i += 512) {
                const float* ap = &A[i*SA + kbb];
                float a0 = sR[i][0], a1 = sR[i][1];
                #pragma unroll
                for (int j = 0; j < PBW; j++) {
                    float u = ap[j];
                    a0 = fmaf(-u, sX[j][0], a0);
                    a1 = fmaf(-u, sX[j][1], a1);
                }
                sR[i][0] = a0; sR[i][1] = a1;
            }
            __syncthreads();
        }

        // pack for eval: negate src coords; weights raw (analytic-Jacobian eval)
        if (tid < KC) {
            float2 s = sSrc[tid];
            g_cw[n][tid] = make_float4(-s.x, -s.y, sR[tid][0], sR[tid][1]);
        }
        if (tid >= KC && tid < NA) {
            int r = tid - KC;
            g_aff[n][r*2+0] = sR[tid][0];
            g_aff[n][r*2+1] = sR[tid][1];
        }
    }
}

// ============================================================
// Kernel 3: TPS eval via ANALYTIC Jacobian + compose.
// dU/dx = ddx*(ln(r2+eps)+1) — replaces the 3-point finite difference,
// cutting MUFU 3x and FMA ~2x. Affine Jacobian is constant (seeds accs).
// ============================================================
__global__ void __launch_bounds__(256) k_eval(float* __restrict__ out)
{
    __shared__ __align__(16) float4 scw[KC];
    __shared__ float saff[6];

    const int bpn = HW/256;
    int n  = blockIdx.x / bpn;
    int p  = (blockIdx.x - n*bpn)*256 + threadIdx.x;

    for (int i = threadIdx.x; i < KC; i += 256) scw[i] = g_cw[n][i];
    if (threadIdx.x < 6) saff[threadIdx.x] = g_aff[n][threadIdx.x];
    __syncthreads();

    int gi = n*HW + p;
    float qx = g_cx[gi], qy = g_cy[gi];
    float m  = g_m[gi];

    unsigned long long qxy;
    PACK2(qxy, qx, qy);

    // J = [[a, c], [b, d]];  accAB = (a,b) = d(c0x,c0y)/dx, accCD = (c,d) = d/dy
    unsigned long long accAB, accCD;
    PACK2(accAB, saff[2], saff[3]);
    PACK2(accCD, saff[4], saff[5]);

    const unsigned long long* scw2 = (const unsigned long long*)scw;
    const float LN2 = 0.69314718056f;

    #pragma unroll 4
    for (int c = 0; c < KC; c++) {
        unsigned long long nsxy = scw2[c*2+0];     // (-sx, -sy)
        unsigned long long wzw  = scw2[c*2+1];     // (w0, w1)

        unsigned long long dd;  ADD2(dd, qxy, nsxy);      // (ddx, ddy)
        float ddx, ddy; UNPACK2(ddx, ddy, dd);
        float r2e = fmaf(ddx, ddx, fmaf(ddy, ddy, EPSc));
        float g   = fmaf(LN2, __log2f(r2e), 1.0f);        // ln(r2e)+1
        float tx = ddx*g, ty = ddy*g;

        unsigned long long tx2, ty2;
        PACK2(tx2, tx, tx);
        PACK2(ty2, ty, ty);
        FMA2(accAB, tx2, wzw, accAB);
        FMA2(accCD, ty2, wzw, accCD);
    }

    float av, bv, cv, dv;
    UNPACK2(av, bv, accAB);
    UNPACK2(cv, dv, accCD);

    float d0 = g_dx[gi], d1 = g_dy[gi];
    float dn0 = av*d0 + cv*d1;
    float dn1 = bv*d0 + dv*d1;

    int w = p % Wd, h = p / Wd;
    float bx = w*STEPc - 1.0f;
    float by = h*STEPc - 1.0f;
    float o0 = (bx + dn0)*m - 2.0f*(1.0f - m);
    float o1 = (by + dn1)*m - 2.0f*(1.0f - m);
    out[gi*2+0] = o0;
    out[gi*2+1] = o1;
}

// ============================================================
extern "C" void kernel_launch(void* const* d_in, const int* in_sizes, int n_in,
                              void* d_out, int out_size)
{
    const float* in0 = (const float*)d_in[0];
    const float* in1 = (const float*)d_in[1];
    const float* duv;
    const float* uv;
    if (in_sizes[0] == 2*HW) { duv = in0; uv = in1; }
    else                     { duv = in1; uv = in0; }

    float* out = (float*)d_out;
    float* out_mask = out + (size_t)Nb*HW*2;

    k_prepare<<<(Nb*HW + 255)/256, 256>>>(duv, uv, out_mask);
    k_lu<<<Nb*CLU, 512>>>();
    k_eval<<<Nb*(HW/256), 256>>>(out);
}

// round 15
// speedup vs baseline: 4.4740x; 1.0760x over previous
#include <cuda_runtime.h>
#include <cooperative_groups.h>

namespace cg = cooperative_groups;

#define Hh 192
#define Wd 192
#define HW (Hh*Wd)
#define Nb 6
#define KG 20
#define KC 400
#define NA 403          // 400 ctrl + 3 affine
#define SA 408          // padded row stride (403,404 = rhs, 405..407 pad)
#define PBW 32          // panel/block width
#define NPAN 13
#define LAMBDc 100.0f
#define BIGc 100000000.0f
#define EPSc 1e-9f
#define STEPc (2.0f/191.0f)

#define PACK2(out, lo, hi) \
    asm("mov.b64 %0, {%1, %2};" : "=l"(out) : "f"(lo), "f"(hi))
#define UNPACK2(lo, hi, in) \
    asm("mov.b64 {%0, %1}, %2;" : "=f"(lo), "=f"(hi) : "l"(in))
#define ADD2(out, a, b) \
    asm("add.rn.f32x2 %0, %1, %2;" : "=l"(out) : "l"(a), "l"(b))
#define MUL2(out, a, b) \
    asm("mul.rn.f32x2 %0, %1, %2;" : "=l"(out) : "l"(a), "l"(b))
#define FMA2(out, a, b, c) \
    asm("fma.rn.f32x2 %0, %1, %2, %3;" : "=l"(out) : "l"(a), "l"(b), "l"(c))

__device__ __constant__ int c_ctrl[KG] =
    {0,10,20,30,40,50,60,70,80,90,101,111,121,131,141,151,161,171,181,191};

// ------- scratch (device globals, no allocs) -------
__device__ float g_cx[Nb*HW];
__device__ float g_cy[Nb*HW];
__device__ float g_dx[Nb*HW];
__device__ float g_dy[Nb*HW];
__device__ float g_m [Nb*HW];
__device__ __align__(16) float g_A[Nb][NA][SA];   // ~3.95 MB, L2 resident
__device__ __align__(16) float4 g_cw[Nb][KC];     // (-sx, -sy, w0, w1)
__device__ float g_aff[Nb][6];

// ============================================================
// Kernel 1: fused analytic-field backward warp
// ============================================================
__global__ void k_prepare(const float* __restrict__ duv,
                          const float* __restrict__ uv,
                          float* __restrict__ out_mask)
{
    int idx = blockIdx.x*blockDim.x + threadIdx.x;
    if (idx >= Nb*HW) return;

    float gx = uv[idx*2+0];
    float gy = uv[idx*2+1];
    float x = (gx + 1.0f)*0.5f*(Wd-1);
    float y = (gy + 1.0f)*0.5f*(Hh-1);
    float x0f = floorf(x), y0f = floorf(y);
    float wx = x - x0f,   wy = y - y0f;
    int x0 = (int)x0f, y0 = (int)y0f;

    float acx=0.f, acy=0.f, adx=0.f, ady=0.f, am=0.f;

    #pragma unroll
    for (int cyi = 0; cyi < 2; cyi++) {
        #pragma unroll
        for (int cxi = 0; cxi < 2; cxi++) {
            int xi = x0 + cxi, yi = y0 + cyi;
            float w = (cxi ? wx : 1.0f-wx) * (cyi ? wy : 1.0f-wy);
            if (xi >= 0 && xi < Wd && yi >= 0 && yi < Hh) {
                float du0 = duv[(yi*Wd+xi)*2+0];
                float du1 = duv[(yi*Wd+xi)*2+1];
                float vpix = (fabsf(du0) <= 1.0f && fabsf(du1) <= 1.0f) ? 1.0f : 0.0f;
                float bx = xi*STEPc - 1.0f;
                float by = yi*STEPc - 1.0f;
                acx += w*bx;
                acy += w*by;
                adx += w*(du0-bx)*vpix;
                ady += w*(du1-by)*vpix;
                am  += w*vpix;
            }
        }
    }
    float mth = (am > 0.5f) ? 1.0f : 0.0f;
    g_cx[idx]=acx; g_cy[idx]=acy; g_dx[idx]=adx; g_dy[idx]=ady; g_m[idx]=mth;
    out_mask[idx] = mth;
}

// ============================================================
// Kernel 2: ONE launch — build + blocked LU + back-sub.
// grid = Nb*clu CTAs, runtime cluster (clu,1,1): one cluster per batch.
// clu = 16 when the HW accepts non-portable clusters, else 8.
// ============================================================
__global__ void __launch_bounds__(512, 1)
k_lu(int clu)
{
    cg::cluster_group cluster = cg::this_cluster();

    const int n    = blockIdx.x / clu;
    const int rank = blockIdx.x - n*clu;
    const int tid  = threadIdx.x;
    const int lane = tid & 31;
    const int wid  = tid >> 5;
    float* A = &g_A[n][0][0];

    __shared__ float  sBlk[PBW][PBW+1];          // L\U block (logical order)
    __shared__ float  sInvD[PBW];
    __shared__ int    sPerm[PBW];
    __shared__ float2 sSrc[KC];
    __shared__ float  sM[KC];
    __shared__ __align__(16) float sLt[PBW][132];   // GEMM L21 tile, kk-major
    __shared__ __align__(16) float sU[PBW][68];     // GEMM U12 tile
    __shared__ float  sR[NA][2];                 // back-sub rhs
    __shared__ float  sX[PBW][2];                // back-sub block solution

    // ---------- build augmented matrix (rows i == rank mod clu) ----------
    for (int i = tid; i < KC; i += 512) {
        int pix = c_ctrl[i/KG]*Wd + c_ctrl[i%KG];
        sSrc[i] = make_float2(g_cx[n*HW+pix], g_cy[n*HW+pix]);
        sM[i]   = g_m[n*HW+pix];
    }
    __syncthreads();
    for (int i = rank; i < NA; i += clu) {
        for (int j = tid; j < SA; j += 512) {
            float v = 0.0f;
            if (j < 405) {
                if (i < KC) {
                    float2 si = sSrc[i];
                    if (j < KC) {
                        float2 sj = sSrc[j];
                        float ddx = si.x - sj.x, ddy = si.y - sj.y;
                        float r2 = ddx*ddx + ddy*ddy;
                        v = 0.5f*r2*__logf(r2 + EPSc);
                        if (i == j) v += LAMBDc + BIGc*(1.0f - sM[i]);
                    } else if (j == 400) v = 1.0f;
                    else if (j == 401) v = si.x;
                    else if (j == 402) v = si.y;
                    else if (j == 403) v = c_ctrl[i%KG]*STEPc - 1.0f;
                    else               v = c_ctrl[i/KG]*STEPc - 1.0f;
                } else {
                    int r = i - KC;
                    if (j < KC) {
                        float2 sj = sSrc[j];
                        v = (r==0) ? 1.0f : ((r==1) ? sj.x : sj.y);
                    }
                }
            }
            A[i*SA + j] = v;
        }
    }
    cluster.sync();

    // ---------- panel loop ----------
    for (int pan = 0; pan < NPAN; pan++) {
        const int kb = pan*PBW;
        const int bw = (NA - kb < PBW) ? (NA - kb) : PBW;
        const int ke = kb + bw;
        const int M  = NA - ke;
        const int Lw = 405 - ke;

        // zero block smem (padded region must be 0 for guard-free chains)
        for (int i = tid; i < PBW*(PBW+1); i += 512) (&sBlk[0][0])[i] = 0.0f;
        if (tid < PBW) { sInvD[tid] = 0.0f; sPerm[tid] = tid; }
        __syncthreads();

        // ---- 32x32 register LU with in-block pivoting (warp 0, replicated
        //      in every CTA — identical deterministic result, no broadcast) ----
        if (wid == 0) {
            float a[PBW];
            #pragma unroll
            for (int j = 0; j < PBW; j++)
                a[j] = (lane < bw && j < bw) ? A[(kb+lane)*SA + kb + j] : 0.0f;
            bool mydone = (lane >= bw);
            int myslot = -1;
            #pragma unroll
            for (int s = 0; s < PBW; s++) {
                if (s < bw) {
                    float v = mydone ? 0.0f : fabsf(a[s]);
                    unsigned key = mydone ? 0u
                        : ((__float_as_uint(v) & 0xFFFFFFE0u) | (unsigned)lane);
                    unsigned kmax = __reduce_max_sync(0xffffffffu, key);
                    int p = (int)(kmax & 31u);
                    float piv = __shfl_sync(0xffffffffu, a[s], p);
                    float inv = 1.0f / piv;
                    if (lane == p) { mydone = true; myslot = s; sPerm[s] = lane; sInvD[s] = inv; }
                    float f = mydone ? 0.0f : a[s]*inv;
                    if (!mydone) a[s] = f;
                    #pragma unroll
                    for (int j = 0; j < PBW; j++) {
                        if (j > s) {
                            float u = __shfl_sync(0xffffffffu, a[j], p);
                            if (!mydone) a[j] = fmaf(-f, u, a[j]);
                        }
                    }
                }
            }
            if (myslot >= 0) {
                #pragma unroll
                for (int j = 0; j < PBW; j++) sBlk[myslot][j] = a[j];
            }
        }
        __syncthreads();

        // rank 0 writes the factored block back (back-sub needs U11)
        if (rank == 0) {
            for (int idx = tid; idx < bw*bw; idx += 512) {
                int r = idx / bw, j = idx - r*bw;
                A[(kb+r)*SA + kb + j] = sBlk[r][j];
            }
        }

        // ---- U12 = L11^{-1} P A12 : one column per lane, INTERLEAVED so
        //      active warp-slots spread across all clu CTAs ----
        {
            int jb = wid*clu + rank;           // cluster warp slots
            int j = jb*PBW + lane;
            if (j < Lw) {
                float c[PBW];
                #pragma unroll
                for (int r = 0; r < PBW; r++) {
                    int pr = (r < bw) ? sPerm[r] : 0;
                    c[r] = A[(kb + pr)*SA + ke + j];
                }
                #pragma unroll
                for (int s = 0; s < PBW-1; s++) {
                    #pragma unroll
                    for (int r = s+1; r < PBW; r++)
                        c[r] = fmaf(-sBlk[r][s], c[s], c[r]);
                }
                #pragma unroll
                for (int r = 0; r < PBW; r++)
                    if (r < bw) A[(kb+r)*SA + ke + j] = c[r];
            }
        }

        // ---- L21 = A21 U11^{-1} : one row per thread, INTERLEAVED ----
        // (only runs when M>0, i.e. bw==32 — no partial-width guards needed)
        {
            int tb = wid*clu + rank;
            int t = tb*PBW + lane;
            if (t < M) {
                float row[PBW];
                float* ap = &A[(ke+t)*SA + kb];
                #pragma unroll
                for (int j = 0; j < PBW; j++) row[j] = ap[j];
                #pragma unroll
                for (int s = 0; s < PBW; s++) {
                    float xs = row[s]*sInvD[s];
                    row[s] = xs;
                    #pragma unroll
                    for (int j = s+1; j < PBW; j++)
                        row[j] = fmaf(-xs, sBlk[s][j], row[j]);
                }
                #pragma unroll
                for (int j = 0; j < PBW; j++) ap[j] = row[j];
            }
        }
        cluster.sync();   // TRSM results visible cluster-wide

        // ---- trailing GEMM  A22 -= L21 @ U12  (128x64 tiles, k=32) ----
        if (M > 0) {
            const int nrt = (M + 127) >> 7;
            const int nct = (Lw + 63) >> 6;
            const int ntiles = nrt*nct;
            const int tx = tid & 15, ty = tid >> 4;   // 16 x 32 thread grid
            for (int tile = rank; tile < ntiles; tile += clu) {
                int tr = tile / nct, tc = tile - tr*nct;
                int i0 = tr << 7;
                int cb = tc << 6;
                int c0 = ke + cb;
                // load L (kk-major transpose: coalesced global, aligned LDS.128)
                for (int idx = tid; idx < 128*PBW; idx += 512) {
                    int r = idx >> 5, kk = idx & 31;
                    sLt[kk][r] = (i0 + r < M) ? A[(ke+i0+r)*SA + kb + kk] : 0.0f;
                }
                for (int idx = tid; idx < PBW*64; idx += 512) {
                    int kk = idx >> 6, c = idx & 63;
                    sU[kk][c] = (cb + c < Lw) ? A[(kb+kk)*SA + c0 + c] : 0.0f;
                }
                __syncthreads();

                int c4 = c0 + tx*4;
                bool colok = (c4 < 405);          // pad cols 405..407 writable
                float4 acc[4];
                bool rowok[4];
                #pragma unroll
                for (int i = 0; i < 4; i++) {
                    int gr = ke + i0 + ty*4 + i;
                    rowok[i] = (gr < NA);
                    acc[i] = (rowok[i] && colok) ? *(const float4*)&A[gr*SA + c4]
                                                 : make_float4(0,0,0,0);
                }
                #pragma unroll
                for (int kk = 0; kk < PBW; kk++) {
                    float4 u = *(const float4*)&sU[kk][tx*4];
                    float4 l = *(const float4*)&sLt[kk][ty*4];
                    float lv[4] = {l.x, l.y, l.z, l.w};
                    #pragma unroll
                    for (int i = 0; i < 4; i++) {
                        acc[i].x = fmaf(-lv[i], u.x, acc[i].x);
                        acc[i].y = fmaf(-lv[i], u.y, acc[i].y);
                        acc[i].z = fmaf(-lv[i], u.z, acc[i].z);
                        acc[i].w = fmaf(-lv[i], u.w, acc[i].w);
                    }
                }
                if (colok) {
                    #pragma unroll
                    for (int i = 0; i < 4; i++) {
                        int gr = ke + i0 + ty*4 + i;
                        if (rowok[i]) *(float4*)&A[gr*SA + c4] = acc[i];
                    }
                }
                __syncthreads();
            }
        }
        cluster.sync();   // GEMM visible for next panel's LU
    }

    // ---------- back substitution: 32-wide warp-systolic blocks (rank 0) ----------
    if (rank == 0) {
        for (int i = tid; i < NA; i += 512) {
            sR[i][0] = A[i*SA + 403];
            sR[i][1] = A[i*SA + 404];
        }
        __syncthreads();

        for (int kbb = (NPAN-1)*PBW; kbb >= 0; kbb -= PBW) {
            int nact = NA - kbb; if (nact > PBW) nact = PBW;   // 19 then 32s
            if (wid == 0) {
                // lane r holds row (kbb+r) of the U diag block; identity-pad
                float t[PBW];
                float x0 = 0.f, x1 = 0.f;
                int gr = kbb + lane;
                bool rok = (lane < nact);
                #pragma unroll
                for (int j = 0; j < PBW; j++) {
                    bool ok = rok && (j < nact);
                    t[j] = ok ? A[gr*SA + kbb + j] : ((j == lane) ? 1.0f : 0.0f);
                }
                if (rok) { x0 = sR[gr][0]; x1 = sR[gr][1]; }
                #pragma unroll
                for (int k = PBW-1; k >= 0; k--) {
                    float xk0 = 0.f, xk1 = 0.f;
                    if (lane == k) {
                        float iv = 1.0f / t[k];
                        xk0 = x0*iv; xk1 = x1*iv;
                        x0 = xk0; x1 = xk1;
                    }
                    xk0 = __shfl_sync(0xffffffffu, xk0, k);
                    xk1 = __shfl_sync(0xffffffffu, xk1, k);
                    if (lane < k) {
                        x0 = fmaf(-t[k], xk0, x0);
                        x1 = fmaf(-t[k], xk1, x1);
                    }
                }
                if (rok) { sR[gr][0] = x0; sR[gr][1] = x1; }
                sX[lane][0] = rok ? x0 : 0.0f;
                sX[lane][1] = rok ? x1 : 0.0f;
            }
            __syncthreads();
            // rank-32 update of rows above (sX zero-padded → unguarded j loop;
            // stray cols 403/404 reads are finite rhs values multiplied by 0)
            for (int i = tid; i < kbb; i += 512) {
                const float* ap = &A[i*SA + kbb];
                float a0 = sR[i][0], a1 = sR[i][1];
                #pragma unroll
                for (int j = 0; j < PBW; j++) {
                    float u = ap[j];
                    a0 = fmaf(-u, sX[j][0], a0);
                    a1 = fmaf(-u, sX[j][1], a1);
                }
                sR[i][0] = a0; sR[i][1] = a1;
            }
            __syncthreads();
        }

        // pack for eval: negate src coords; weights raw (analytic-Jacobian eval)
        if (tid < KC) {
            float2 s = sSrc[tid];
            g_cw[n][tid] = make_float4(-s.x, -s.y, sR[tid][0], sR[tid][1]);
        }
        if (tid >= KC && tid < NA) {
            int r = tid - KC;
            g_aff[n][r*2+0] = sR[tid][0];
            g_aff[n][r*2+1] = sR[tid][1];
        }
    }
}

// ============================================================
// Kernel 3: TPS eval via ANALYTIC Jacobian + compose.
// ============================================================
__global__ void __launch_bounds__(256) k_eval(float* __restrict__ out)
{
    __shared__ __align__(16) float4 scw[KC];
    __shared__ float saff[6];

    const int bpn = HW/256;
    int n  = blockIdx.x / bpn;
    int p  = (blockIdx.x - n*bpn)*256 + threadIdx.x;

    for (int i = threadIdx.x; i < KC; i += 256) scw[i] = g_cw[n][i];
    if (threadIdx.x < 6) saff[threadIdx.x] = g_aff[n][threadIdx.x];
    __syncthreads();

    int gi = n*HW + p;
    float qx = g_cx[gi], qy = g_cy[gi];
    float m  = g_m[gi];

    unsigned long long qxy;
    PACK2(qxy, qx, qy);

    // J = [[a, c], [b, d]];  accAB = (a,b) = d(c0x,c0y)/dx, accCD = (c,d) = d/dy
    unsigned long long accAB, accCD;
    PACK2(accAB, saff[2], saff[3]);
    PACK2(accCD, saff[4], saff[5]);

    const unsigned long long* scw2 = (const unsigned long long*)scw;
    const float LN2 = 0.69314718056f;

    #pragma unroll 4
    for (int c = 0; c < KC; c++) {
        unsigned long long nsxy = scw2[c*2+0];     // (-sx, -sy)
        unsigned long long wzw  = scw2[c*2+1];     // (w0, w1)

        unsigned long long dd;  ADD2(dd, qxy, nsxy);      // (ddx, ddy)
        float ddx, ddy; UNPACK2(ddx, ddy, dd);
        float r2e = fmaf(ddx, ddx, fmaf(ddy, ddy, EPSc));
        float g   = fmaf(LN2, __log2f(r2e), 1.0f);        // ln(r2e)+1
        float tx = ddx*g, ty = ddy*g;

        unsigned long long tx2, ty2;
        PACK2(tx2, tx, tx);
        PACK2(ty2, ty, ty);
        FMA2(accAB, tx2, wzw, accAB);
        FMA2(accCD, ty2, wzw, accCD);
    }

    float av, bv, cv, dv;
    UNPACK2(av, bv, accAB);
    UNPACK2(cv, dv, accCD);

    float d0 = g_dx[gi], d1 = g_dy[gi];
    float dn0 = av*d0 + cv*d1;
    float dn1 = bv*d0 + dv*d1;

    int w = p % Wd, h = p / Wd;
    float bx = w*STEPc - 1.0f;
    float by = h*STEPc - 1.0f;
    float o0 = (bx + dn0)*m - 2.0f*(1.0f - m);
    float o1 = (by + dn1)*m - 2.0f*(1.0f - m);
    out[gi*2+0] = o0;
    out[gi*2+1] = o1;
}

// ============================================================
extern "C" void kernel_launch(void* const* d_in, const int* in_sizes, int n_in,
                              void* d_out, int out_size)
{
    const float* in0 = (const float*)d_in[0];
    const float* in1 = (const float*)d_in[1];
    const float* duv;
    const float* uv;
    if (in_sizes[0] == 2*HW) { duv = in0; uv = in1; }
    else                     { duv = in1; uv = in0; }

    float* out = (float*)d_out;
    float* out_mask = out + (size_t)Nb*HW*2;

    k_prepare<<<(Nb*HW + 255)/256, 256>>>(duv, uv, out_mask);

    // ---- k_lu with runtime cluster size: try 16 (non-portable), else 8 ----
    cudaFuncSetAttribute(k_lu, cudaFuncAttributeNonPortableClusterSizeAllowed, 1);

    cudaLaunchConfig_t cfg = {};
    cudaLaunchAttribute at[1];
    at[0].id = cudaLaunchAttributeClusterDimension;
    at[0].val.clusterDim.x = 16;
    at[0].val.clusterDim.y = 1;
    at[0].val.clusterDim.z = 1;
    cfg.attrs = at;
    cfg.numAttrs = 1;
    cfg.gridDim = dim3(Nb*16, 1, 1);
    cfg.blockDim = dim3(512, 1, 1);
    cfg.dynamicSmemBytes = 0;
    cfg.stream = 0;

    int nclu = 0;
    cudaError_t qe = cudaOccupancyMaxActiveClusters(&nclu, k_lu, &cfg);
    int clu = (qe == cudaSuccess && nclu > 0) ? 16 : 8;
    if (clu == 8) {
        (void)cudaGetLastError();   // clear any query error
        at[0].val.clusterDim.x = 8;
        cfg.gridDim = dim3(Nb*8, 1, 1);
    }
    cudaLaunchKernelEx(&cfg, k_lu, clu);

    k_eval<<<Nb*(HW/256), 256>>>(out);
}

// round 16
// speedup vs baseline: 4.5055x; 1.0070x over previous
#include <cuda_runtime.h>
#include <cooperative_groups.h>

namespace cg = cooperative_groups;

#define Hh 192
#define Wd 192
#define HW (Hh*Wd)
#define Nb 6
#define KG 20
#define KC 400
#define NA 403          // 400 ctrl + 3 affine
#define SA 408          // padded row stride (403,404 = rhs, 405..407 pad)
#define PBW 32          // panel/block width
#define NPAN 13
#define LAMBDc 100.0f
#define BIGc 100000000.0f
#define EPSc 1e-9f
#define STEPc (2.0f/191.0f)

#define PACK2(out, lo, hi) \
    asm("mov.b64 %0, {%1, %2};" : "=l"(out) : "f"(lo), "f"(hi))
#define UNPACK2(lo, hi, in) \
    asm("mov.b64 {%0, %1}, %2;" : "=f"(lo), "=f"(hi) : "l"(in))
#define ADD2(out, a, b) \
    asm("add.rn.f32x2 %0, %1, %2;" : "=l"(out) : "l"(a), "l"(b))
#define FMA2(out, a, b, c) \
    asm("fma.rn.f32x2 %0, %1, %2, %3;" : "=l"(out) : "l"(a), "l"(b), "l"(c))

__device__ __constant__ int c_ctrl[KG] =
    {0,10,20,30,40,50,60,70,80,90,101,111,121,131,141,151,161,171,181,191};

// ------- scratch (device globals, no allocs) -------
__device__ float g_cx[Nb*HW];
__device__ float g_cy[Nb*HW];
__device__ float g_dx[Nb*HW];
__device__ float g_dy[Nb*HW];
__device__ float g_m [Nb*HW];
__device__ __align__(16) float g_A[Nb][NA][SA];   // ~3.95 MB, L2 resident
__device__ __align__(16) float g_nlu[Nb][1088];   // lookahead LU: [0,1056) factors (32x33), [1056,1088) invD
__device__ int g_nluPerm[Nb][PBW];
__device__ __align__(16) float4 g_cw[Nb][KC];     // (-sx, -sy, w0, w1)
__device__ float g_aff[Nb][6];

// ============================================================
// Kernel 1: fused analytic-field backward warp
// ============================================================
__global__ void k_prepare(const float* __restrict__ duv,
                          const float* __restrict__ uv,
                          float* __restrict__ out_mask)
{
    int idx = blockIdx.x*blockDim.x + threadIdx.x;
    if (idx >= Nb*HW) return;

    float gx = uv[idx*2+0];
    float gy = uv[idx*2+1];
    float x = (gx + 1.0f)*0.5f*(Wd-1);
    float y = (gy + 1.0f)*0.5f*(Hh-1);
    float x0f = floorf(x), y0f = floorf(y);
    float wx = x - x0f,   wy = y - y0f;
    int x0 = (int)x0f, y0 = (int)y0f;

    float acx=0.f, acy=0.f, adx=0.f, ady=0.f, am=0.f;

    #pragma unroll
    for (int cyi = 0; cyi < 2; cyi++) {
        #pragma unroll
        for (int cxi = 0; cxi < 2; cxi++) {
            int xi = x0 + cxi, yi = y0 + cyi;
            float w = (cxi ? wx : 1.0f-wx) * (cyi ? wy : 1.0f-wy);
            if (xi >= 0 && xi < Wd && yi >= 0 && yi < Hh) {
                float du0 = duv[(yi*Wd+xi)*2+0];
                float du1 = duv[(yi*Wd+xi)*2+1];
                float vpix = (fabsf(du0) <= 1.0f && fabsf(du1) <= 1.0f) ? 1.0f : 0.0f;
                float bx = xi*STEPc - 1.0f;
                float by = yi*STEPc - 1.0f;
                acx += w*bx;
                acy += w*by;
                adx += w*(du0-bx)*vpix;
                ady += w*(du1-by)*vpix;
                am  += w*vpix;
            }
        }
    }
    float mth = (am > 0.5f) ? 1.0f : 0.0f;
    g_cx[idx]=acx; g_cy[idx]=acy; g_dx[idx]=adx; g_dy[idx]=ady; g_m[idx]=mth;
    out_mask[idx] = mth;
}

// 32x32 register LU with in-block pivoting, executed by one warp.
// src(lane, j) supplied by caller; results: factor rows via myslot -> out
// callback responsibility of caller; inv/perm in given smem arrays.
// (kept as a macro-ish inline to allow two call sites with different sources)
// ============================================================
// Kernel 2: ONE launch — build + blocked LU (with LU lookahead) + back-sub.
// grid = Nb*clu CTAs, runtime cluster (clu,1,1): one cluster per batch.
// Rank clu-1 computes the NEXT panel's LU (mini-GEMM + register LU) while
// ranks 0..clu-2 run the trailing GEMM; factors broadcast via g_nlu + the
// existing end-of-panel cluster.sync. Bitwise identical to the non-lookahead
// factorization (same fma order).
// ============================================================
__global__ void __launch_bounds__(512, 1)
k_lu(int clu)
{
    cg::cluster_group cluster = cg::this_cluster();

    const int n    = blockIdx.x / clu;
    const int rank = blockIdx.x - n*clu;
    const int lurank = clu - 1;
    const int tid  = threadIdx.x;
    const int lane = tid & 31;
    const int wid  = tid >> 5;
    float* A = &g_A[n][0][0];

    __shared__ float  sBlk[PBW][PBW+1];          // L\U block (logical order)
    __shared__ float  sInvD[PBW];
    __shared__ int    sPerm[PBW];
    __shared__ float  sInvD2[PBW];
    __shared__ int    sPerm2[PBW];
    __shared__ float2 sSrc[KC];
    __shared__ float  sM[KC];
    __shared__ __align__(16) float sLt[PBW][132];   // GEMM L21 tile, kk-major
    __shared__ __align__(16) float sU[PBW][68];     // GEMM U12 tile
    __shared__ float  sR[NA][2];                 // back-sub rhs
    __shared__ float  sX[PBW][2];                // back-sub block solution

    // lookahead scratch aliases sLt (lurank never runs the main GEMM)
    float (*sNxt)[32] = (float(*)[32])&sLt[0][0];    // [32][32]
    float (*sML)[32]  = (float(*)[32])&sLt[8][0];    // offset 1056 floats
    float (*sMU)[32]  = (float(*)[32])&sLt[16][0];   // offset 2112 floats

    // ---------- build augmented matrix (rows i == rank mod clu) ----------
    for (int i = tid; i < KC; i += 512) {
        int pix = c_ctrl[i/KG]*Wd + c_ctrl[i%KG];
        sSrc[i] = make_float2(g_cx[n*HW+pix], g_cy[n*HW+pix]);
        sM[i]   = g_m[n*HW+pix];
    }
    __syncthreads();
    for (int i = rank; i < NA; i += clu) {
        for (int j = tid; j < SA; j += 512) {
            float v = 0.0f;
            if (j < 405) {
                if (i < KC) {
                    float2 si = sSrc[i];
                    if (j < KC) {
                        float2 sj = sSrc[j];
                        float ddx = si.x - sj.x, ddy = si.y - sj.y;
                        float r2 = ddx*ddx + ddy*ddy;
                        v = 0.5f*r2*__logf(r2 + EPSc);
                        if (i == j) v += LAMBDc + BIGc*(1.0f - sM[i]);
                    } else if (j == 400) v = 1.0f;
                    else if (j == 401) v = si.x;
                    else if (j == 402) v = si.y;
                    else if (j == 403) v = c_ctrl[i%KG]*STEPc - 1.0f;
                    else               v = c_ctrl[i/KG]*STEPc - 1.0f;
                } else {
                    int r = i - KC;
                    if (j < KC) {
                        float2 sj = sSrc[j];
                        v = (r==0) ? 1.0f : ((r==1) ? sj.x : sj.y);
                    }
                }
            }
            A[i*SA + j] = v;
        }
    }
    cluster.sync();

    // ---------- prologue: panel 0 LU (replicated warp0, from global) ----------
    {
        for (int i = tid; i < PBW*(PBW+1); i += 512) (&sBlk[0][0])[i] = 0.0f;
        if (tid < PBW) { sInvD[tid] = 0.0f; sPerm[tid] = tid; }
        __syncthreads();
        if (wid == 0) {
            float a[PBW];
            #pragma unroll
            for (int j = 0; j < PBW; j++) a[j] = A[lane*SA + j];
            bool mydone = false;
            int myslot = -1;
            #pragma unroll
            for (int s = 0; s < PBW; s++) {
                float v = mydone ? 0.0f : fabsf(a[s]);
                unsigned key = mydone ? 0u
                    : ((__float_as_uint(v) & 0xFFFFFFE0u) | (unsigned)lane);
                unsigned kmax = __reduce_max_sync(0xffffffffu, key);
                int p = (int)(kmax & 31u);
                float piv = __shfl_sync(0xffffffffu, a[s], p);
                float inv = 1.0f / piv;
                if (lane == p) { mydone = true; myslot = s; sPerm[s] = lane; sInvD[s] = inv; }
                float f = mydone ? 0.0f : a[s]*inv;
                if (!mydone) a[s] = f;
                #pragma unroll
                for (int j = 0; j < PBW; j++) {
                    if (j > s) {
                        float u = __shfl_sync(0xffffffffu, a[j], p);
                        if (!mydone) a[j] = fmaf(-f, u, a[j]);
                    }
                }
            }
            if (myslot >= 0) {
                #pragma unroll
                for (int j = 0; j < PBW; j++) sBlk[myslot][j] = a[j];
            }
        }
        __syncthreads();
    }

    // ---------- panel loop ----------
    for (int pan = 0; pan < NPAN; pan++) {
        const int kb = pan*PBW;
        const int bw = (NA - kb < PBW) ? (NA - kb) : PBW;
        const int ke = kb + bw;
        const int M  = NA - ke;
        const int Lw = 405 - ke;
        const bool hasNext = (pan + 1 < NPAN);
        const int kb2 = ke;
        const int bw2 = hasNext ? ((NA - kb2 < PBW) ? (NA - kb2) : PBW) : 0;

        // rank 0 persists current panel factors (for back-sub); diag square
        // is not read by any other phase this panel.
        if (rank == 0) {
            for (int idx = tid; idx < bw*bw; idx += 512) {
                int r = idx / bw, j = idx - r*bw;
                A[(kb+r)*SA + kb + j] = sBlk[r][j];
            }
        }

        // ---- U12 = L11^{-1} P A12 : one column per lane, interleaved ----
        {
            int jb = wid*clu + rank;
            int j = jb*PBW + lane;
            if (j < Lw) {
                float c[PBW];
                #pragma unroll
                for (int r = 0; r < PBW; r++) {
                    int pr = (r < bw) ? sPerm[r] : 0;
                    c[r] = A[(kb + pr)*SA + ke + j];
                }
                #pragma unroll
                for (int s = 0; s < PBW-1; s++) {
                    #pragma unroll
                    for (int r = s+1; r < PBW; r++)
                        c[r] = fmaf(-sBlk[r][s], c[s], c[r]);
                }
                #pragma unroll
                for (int r = 0; r < PBW; r++)
                    if (r < bw) A[(kb+r)*SA + ke + j] = c[r];
            }
        }

        // ---- L21 = A21 U11^{-1} : one row per thread, interleaved ----
        {
            int tb = wid*clu + rank;
            int t = tb*PBW + lane;
            if (t < M) {
                float row[PBW];
                float* ap = &A[(ke+t)*SA + kb];
                #pragma unroll
                for (int j = 0; j < PBW; j++) row[j] = ap[j];
                #pragma unroll
                for (int s = 0; s < PBW; s++) {
                    float xs = row[s]*sInvD[s];
                    row[s] = xs;
                    #pragma unroll
                    for (int j = s+1; j < PBW; j++)
                        row[j] = fmaf(-xs, sBlk[s][j], row[j]);
                }
                #pragma unroll
                for (int j = 0; j < PBW; j++) ap[j] = row[j];
            }
        }

        // ---- lurank: snapshot raw next-diag BEFORE the sync (the main GEMM
        //      writes this region only after the sync → no race) ----
        if (hasNext && rank == lurank) {
            for (int idx = tid; idx < PBW*PBW; idx += 512) {
                int i = idx >> 5, j = idx & 31;
                sNxt[i][j] = (i < bw2 && j < bw2) ? A[(kb2+i)*SA + kb2 + j] : 0.0f;
            }
        }
        cluster.sync();   // TRSM results visible cluster-wide

        if (hasNext && rank == lurank) {
            // ---- mini-GEMM: next diag -= L21(next rows) @ U12(next cols) ----
            for (int idx = tid; idx < PBW*PBW; idx += 512) {
                int i = idx >> 5, s = idx & 31;
                sML[i][s] = (i < bw2) ? A[(kb2+i)*SA + kb + s] : 0.0f;
            }
            for (int idx = tid; idx < PBW*PBW; idx += 512) {
                int s = idx >> 5, j = idx & 31;
                sMU[s][j] = (j < bw2) ? A[(kb+s)*SA + kb2 + j] : 0.0f;
            }
            __syncthreads();
            for (int idx = tid; idx < PBW*PBW; idx += 512) {
                int i = idx >> 5, j = idx & 31;
                float d = sNxt[i][j];
                #pragma unroll
                for (int s = 0; s < PBW; s++)
                    d = fmaf(-sML[i][s], sMU[s][j], d);
                sNxt[i][j] = d;
            }
            __syncthreads();
            // ---- warp0: register LU on sNxt, publish to g_nlu ----
            if (wid == 0) {
                sInvD2[lane] = 0.0f; sPerm2[lane] = lane;
                __syncwarp();
                float a[PBW];
                #pragma unroll
                for (int j = 0; j < PBW; j++)
                    a[j] = (lane < bw2 && j < bw2) ? sNxt[lane][j] : 0.0f;
                bool mydone = (lane >= bw2);
                int myslot = -1;
                #pragma unroll
                for (int s = 0; s < PBW; s++) {
                    if (s < bw2) {
                        float v = mydone ? 0.0f : fabsf(a[s]);
                        unsigned key = mydone ? 0u
                            : ((__float_as_uint(v) & 0xFFFFFFE0u) | (unsigned)lane);
                        unsigned kmax = __reduce_max_sync(0xffffffffu, key);
                        int p = (int)(kmax & 31u);
                        float piv = __shfl_sync(0xffffffffu, a[s], p);
                        float inv = 1.0f / piv;
                        if (lane == p) { mydone = true; myslot = s; sPerm2[s] = lane; sInvD2[s] = inv; }
                        float f = mydone ? 0.0f : a[s]*inv;
                        if (!mydone) a[s] = f;
                        #pragma unroll
                        for (int j = 0; j < PBW; j++) {
                            if (j > s) {
                                float u = __shfl_sync(0xffffffffu, a[j], p);
                                if (!mydone) a[j] = fmaf(-f, u, a[j]);
                            }
                        }
                    }
                }
                if (myslot >= 0) {
                    #pragma unroll
                    for (int j = 0; j < PBW; j++) g_nlu[n][myslot*33 + j] = a[j];
                } else {
                    #pragma unroll
                    for (int j = 0; j < PBW; j++) g_nlu[n][lane*33 + j] = 0.0f;
                }
                __syncwarp();
                g_nlu[n][1056 + lane] = sInvD2[lane];
                g_nluPerm[n][lane] = sPerm2[lane];
            }
        } else if (M > 0 && rank != lurank) {
            // ---- trailing GEMM  A22 -= L21 @ U12  (128x64 tiles, k=32),
            //      distributed over ranks 0..clu-2 ----
            const int nrt = (M + 127) >> 7;
            const int nct = (Lw + 63) >> 6;
            const int ntiles = nrt*nct;
            const int tx = tid & 15, ty = tid >> 4;
            for (int tile = rank; tile < ntiles; tile += (clu-1)) {
                int tr = tile / nct, tc = tile - tr*nct;
                int i0 = tr << 7;
                int cb = tc << 6;
                int c0 = ke + cb;
                for (int idx = tid; idx < 128*PBW; idx += 512) {
                    int r = idx >> 5, kk = idx & 31;
                    sLt[kk][r] = (i0 + r < M) ? A[(ke+i0+r)*SA + kb + kk] : 0.0f;
                }
                for (int idx = tid; idx < PBW*64; idx += 512) {
                    int kk = idx >> 6, c = idx & 63;
                    sU[kk][c] = (cb + c < Lw) ? A[(kb+kk)*SA + c0 + c] : 0.0f;
                }
                __syncthreads();

                int c4 = c0 + tx*4;
                bool colok = (c4 < 405);
                float4 acc[4];
                bool rowok[4];
                #pragma unroll
                for (int i = 0; i < 4; i++) {
                    int gr = ke + i0 + ty*4 + i;
                    rowok[i] = (gr < NA);
                    acc[i] = (rowok[i] && colok) ? *(const float4*)&A[gr*SA + c4]
                                                 : make_float4(0,0,0,0);
                }
                #pragma unroll
                for (int kk = 0; kk < PBW; kk++) {
                    float4 u = *(const float4*)&sU[kk][tx*4];
                    float4 l = *(const float4*)&sLt[kk][ty*4];
                    float lv[4] = {l.x, l.y, l.z, l.w};
                    #pragma unroll
                    for (int i = 0; i < 4; i++) {
                        acc[i].x = fmaf(-lv[i], u.x, acc[i].x);
                        acc[i].y = fmaf(-lv[i], u.y, acc[i].y);
                        acc[i].z = fmaf(-lv[i], u.z, acc[i].z);
                        acc[i].w = fmaf(-lv[i], u.w, acc[i].w);
                    }
                }
                if (colok) {
                    #pragma unroll
                    for (int i = 0; i < 4; i++) {
                        int gr = ke + i0 + ty*4 + i;
                        if (rowok[i]) *(float4*)&A[gr*SA + c4] = acc[i];
                    }
                }
                __syncthreads();
            }
        }
        cluster.sync();   // GEMM + next-LU visible for next panel

        // ---- all CTAs load next panel's LU (cheap L2 broadcast) ----
        if (hasNext) {
            for (int idx = tid; idx < 1056; idx += 512)
                (&sBlk[0][0])[idx] = g_nlu[n][idx];
            if (tid < PBW) {
                sInvD[tid] = g_nlu[n][1056 + tid];
                sPerm[tid] = g_nluPerm[n][tid];
            }
            __syncthreads();
        }
    }

    // ---------- back substitution: 32-wide warp-systolic blocks (rank 0) ----------
    if (rank == 0) {
        for (int i = tid; i < NA; i += 512) {
            sR[i][0] = A[i*SA + 403];
            sR[i][1] = A[i*SA + 404];
        }
        __syncthreads();

        for (int kbb = (NPAN-1)*PBW; kbb >= 0; kbb -= PBW) {
            int nact = NA - kbb; if (nact > PBW) nact = PBW;
            if (wid == 0) {
                float t[PBW];
                float x0 = 0.f, x1 = 0.f;
                int gr = kbb + lane;
                bool rok = (lane < nact);
                #pragma unroll
                for (int j = 0; j < PBW; j++) {
                    bool ok = rok && (j < nact);
                    t[j] = ok ? A[gr*SA + kbb + j] : ((j == lane) ? 1.0f : 0.0f);
                }
                if (rok) { x0 = sR[gr][0]; x1 = sR[gr][1]; }
                #pragma unroll
                for (int k = PBW-1; k >= 0; k--) {
                    float xk0 = 0.f, xk1 = 0.f;
                    if (lane == k) {
                        float iv = 1.0f / t[k];
                        xk0 = x0*iv; xk1 = x1*iv;
                        x0 = xk0; x1 = xk1;
                    }
                    xk0 = __shfl_sync(0xffffffffu, xk0, k);
                    xk1 = __shfl_sync(0xffffffffu, xk1, k);
                    if (lane < k) {
                        x0 = fmaf(-t[k], xk0, x0);
                        x1 = fmaf(-t[k], xk1, x1);
                    }
                }
                if (rok) { sR[gr][0] = x0; sR[gr][1] = x1; }
                sX[lane][0] = rok ? x0 : 0.0f;
                sX[lane][1] = rok ? x1 : 0.0f;
            }
            __syncthreads();
            for (int i = tid; i < kbb; i += 512) {
                const float* ap = &A[i*SA + kbb];
                float a0 = sR[i][0], a1 = sR[i][1];
                #pragma unroll
                for (int j = 0; j < PBW; j++) {
                    float u = ap[j];
                    a0 = fmaf(-u, sX[j][0], a0);
                    a1 = fmaf(-u, sX[j][1], a1);
                }
                sR[i][0] = a0; sR[i][1] = a1;
            }
            __syncthreads();
        }

        // pack for eval: negate src coords; weights raw (analytic-Jacobian eval)
        if (tid < KC) {
            float2 s = sSrc[tid];
            g_cw[n][tid] = make_float4(-s.x, -s.y, sR[tid][0], sR[tid][1]);
        }
        if (tid >= KC && tid < NA) {
            int r = tid - KC;
            g_aff[n][r*2+0] = sR[tid][0];
            g_aff[n][r*2+1] = sR[tid][1];
        }
    }
}

// ============================================================
// Kernel 3: TPS eval via ANALYTIC Jacobian + compose.
// ============================================================
__global__ void __launch_bounds__(256) k_eval(float* __restrict__ out)
{
    __shared__ __align__(16) float4 scw[KC];
    __shared__ float saff[6];

    const int bpn = HW/256;
    int n  = blockIdx.x / bpn;
    int p  = (blockIdx.x - n*bpn)*256 + threadIdx.x;

    for (int i = threadIdx.x; i < KC; i += 256) scw[i] = g_cw[n][i];
    if (threadIdx.x < 6) saff[threadIdx.x] = g_aff[n][threadIdx.x];
    __syncthreads();

    int gi = n*HW + p;
    float qx = g_cx[gi], qy = g_cy[gi];
    float m  = g_m[gi];

    unsigned long long qxy;
    PACK2(qxy, qx, qy);

    unsigned long long accAB, accCD;
    PACK2(accAB, saff[2], saff[3]);
    PACK2(accCD, saff[4], saff[5]);

    const unsigned long long* scw2 = (const unsigned long long*)scw;
    const float LN2 = 0.69314718056f;

    #pragma unroll 4
    for (int c = 0; c < KC; c++) {
        unsigned long long nsxy = scw2[c*2+0];     // (-sx, -sy)
        unsigned long long wzw  = scw2[c*2+1];     // (w0, w1)

        unsigned long long dd;  ADD2(dd, qxy, nsxy);      // (ddx, ddy)
        float ddx, ddy; UNPACK2(ddx, ddy, dd);
        float r2e = fmaf(ddx, ddx, fmaf(ddy, ddy, EPSc));
        float g   = fmaf(LN2, __log2f(r2e), 1.0f);        // ln(r2e)+1
        float tx = ddx*g, ty = ddy*g;

        unsigned long long tx2, ty2;
        PACK2(tx2, tx, tx);
        PACK2(ty2, ty, ty);
        FMA2(accAB, tx2, wzw, accAB);
        FMA2(accCD, ty2, wzw, accCD);
    }

    float av, bv, cv, dv;
    UNPACK2(av, bv, accAB);
    UNPACK2(cv, dv, accCD);

    float d0 = g_dx[gi], d1 = g_dy[gi];
    float dn0 = av*d0 + cv*d1;
    float dn1 = bv*d0 + dv*d1;

    int w = p % Wd, h = p / Wd;
    float bx = w*STEPc - 1.0f;
    float by = h*STEPc - 1.0f;
    float o0 = (bx + dn0)*m - 2.0f*(1.0f - m);
    float o1 = (by + dn1)*m - 2.0f*(1.0f - m);
    out[gi*2+0] = o0;
    out[gi*2+1] = o1;
}

// ============================================================
extern "C" void kernel_launch(void* const* d_in, const int* in_sizes, int n_in,
                              void* d_out, int out_size)
{
    const float* in0 = (const float*)d_in[0];
    const float* in1 = (const float*)d_in[1];
    const float* duv;
    const float* uv;
    if (in_sizes[0] == 2*HW) { duv = in0; uv = in1; }
    else                     { duv = in1; uv = in0; }

    float* out = (float*)d_out;
    float* out_mask = out + (size_t)Nb*HW*2;

    k_prepare<<<(Nb*HW + 255)/256, 256>>>(duv, uv, out_mask);

    // ---- k_lu with runtime cluster size: try 16 (non-portable), else 8 ----
    cudaFuncSetAttribute(k_lu, cudaFuncAttributeNonPortableClusterSizeAllowed, 1);

    cudaLaunchConfig_t cfg = {};
    cudaLaunchAttribute at[1];
    at[0].id = cudaLaunchAttributeClusterDimension;
    at[0].val.clusterDim.x = 16;
    at[0].val.clusterDim.y = 1;
    at[0].val.clusterDim.z = 1;
    cfg.attrs = at;
    cfg.numAttrs = 1;
    cfg.gridDim = dim3(Nb*16, 1, 1);
    cfg.blockDim = dim3(512, 1, 1);
    cfg.dynamicSmemBytes = 0;
    cfg.stream = 0;

    int nclu = 0;
    cudaError_t qe = cudaOccupancyMaxActiveClusters(&nclu, k_lu, &cfg);
    int clu = (qe == cudaSuccess && nclu > 0) ? 16 : 8;
    if (clu == 8) {
        (void)cudaGetLastError();   // clear any query error
        at[0].val.clusterDim.x = 8;
        cfg.gridDim = dim3(Nb*8, 1, 1);
    }
    cudaLaunchKernelEx(&cfg, k_lu, clu);

    k_eval<<<Nb*(HW/256), 256>>>(out);
}